// round 2
// baseline (speedup 1.0000x reference)
#include <cuda_runtime.h>
#include <math.h>

typedef unsigned long long ull;

#define NN 20000
#define EE 640000
#define HH 128

// ---------------- f32x2 helpers ----------------
__device__ __forceinline__ ull pack2(float x, float y) {
    ull r; asm("mov.b64 %0, {%1, %2};" : "=l"(r) : "f"(x), "f"(y)); return r;
}
__device__ __forceinline__ void unpack2(ull v, float& x, float& y) {
    asm("mov.b64 {%0, %1}, %2;" : "=f"(x), "=f"(y) : "l"(v));
}
__device__ __forceinline__ void fma2(ull& d, ull a, ull b) {
    asm("fma.rn.f32x2 %0, %1, %2, %0;" : "+l"(d) : "l"(a), "l"(b));
}
__device__ __forceinline__ float silu_f(float x) { return x / (1.0f + expf(-x)); }

// ---------------- scratch ----------------
__device__ float g_h0[NN * HH];
__device__ float g_h1[NN * HH];
__device__ float g_equ1[NN * 9];
__device__ float g_fsum[NN * 12];   // stride 12, 9 used
__device__ float g_msum[NN * HH];
__device__ float g_cnt[NN];

// ---------------- tiled GEMM ----------------
// 256 threads; each owns ROWS x 8 output micro-tile (cols as 4 f32x2).
// A in SMEM (lda), W streamed global->WS in 32x128 chunks.
// PERM: msg-MLP input permutation (smem [h_r|h_c|ef|scalar] vs W rows [scalar|h_r|h_c|ef]).
template<int ROWS, int KPAD, bool PERM>
__device__ __forceinline__ void gemm_t(const float* As, int lda,
                                       const float* __restrict__ Wg, int Kvalid,
                                       float* WS, int tx, int wk, int wc,
                                       ull (&acc)[ROWS][4])
{
#pragma unroll 1
    for (int kc = 0; kc < KPAD; kc += 32) {
        int gk = kc + wk;
        float4 v0, v1, v2, v3;
        if (gk < Kvalid) {
            int wrow = gk;
            if (PERM) wrow = (gk < 264) ? gk + 3 : gk - 264;
            const float4* wp = (const float4*)(Wg + (size_t)wrow * 128 + wc);
            v0 = wp[0]; v1 = wp[1]; v2 = wp[2]; v3 = wp[3];
        } else {
            v0 = v1 = v2 = v3 = make_float4(0.f, 0.f, 0.f, 0.f);
        }
        __syncthreads();
        {
            float4* wsp = (float4*)(WS + wk * 128 + wc);
            wsp[0] = v0; wsp[1] = v1; wsp[2] = v2; wsp[3] = v3;
        }
        __syncthreads();
        const float* Arow = As + kc;
        const float* Bcol = WS + tx * 8;
#pragma unroll 4
        for (int kk = 0; kk < 32; kk++) {
            ull b0 = *(const ull*)(Bcol + kk * 128 + 0);
            ull b1 = *(const ull*)(Bcol + kk * 128 + 2);
            ull b2 = *(const ull*)(Bcol + kk * 128 + 4);
            ull b3 = *(const ull*)(Bcol + kk * 128 + 6);
#pragma unroll
            for (int rr = 0; rr < ROWS; rr++) {
                float a = Arow[rr * lda + kk];
                ull ap = pack2(a, a);
                fma2(acc[rr][0], ap, b0);
                fma2(acc[rr][1], ap, b1);
                fma2(acc[rr][2], ap, b2);
                fma2(acc[rr][3], ap, b3);
            }
        }
    }
}

template<int ROWS, bool SILU>
__device__ __forceinline__ void store_act(ull (&acc)[ROWS][4],
                                          const float* __restrict__ bias,
                                          float* dst, int ldd, int tx, int ty)
{
    float bs[8];
    *(float4*)&bs[0] = *(const float4*)(bias + tx * 8);
    *(float4*)&bs[4] = *(const float4*)(bias + tx * 8 + 4);
#pragma unroll
    for (int rr = 0; rr < ROWS; rr++) {
        float* orow = dst + (ty * ROWS + rr) * ldd + tx * 8;
#pragma unroll
        for (int cp = 0; cp < 4; cp++) {
            float x0, x1; unpack2(acc[rr][cp], x0, x1);
            x0 += bs[2 * cp]; x1 += bs[2 * cp + 1];
            if (SILU) { x0 = silu_f(x0); x1 = silu_f(x1); }
            *(float2*)(orow + 2 * cp) = make_float2(x0, x1);
            acc[rr][cp] = 0ull;
        }
    }
}

// ---------------- edge kernel: 128 edges / block ----------------
// smem floats: SIN[128][292]@0 (37376) ; HID[128][132]@0 (reuse) ; MSG@16896 (16896)
//              WS@37376 (4096) ; RIJ[128][12]@41472 (1536) ; CW2s@43008 (128)
#define E_SMEM_FLOATS 43136
#define E_SMEM_BYTES (E_SMEM_FLOATS * 4)

__global__ __launch_bounds__(256, 1)
void edge_kernel(const float* __restrict__ equ, const float* __restrict__ hN,
                 const float* __restrict__ efea,
                 const int* __restrict__ erow, const int* __restrict__ ecol,
                 const float* __restrict__ W1, const float* __restrict__ B1,
                 const float* __restrict__ W2, const float* __restrict__ B2,
                 const float* __restrict__ CW1, const float* __restrict__ CB1,
                 const float* __restrict__ CW2, const float* __restrict__ CB2,
                 float* __restrict__ fsum, float* __restrict__ msum)
{
    extern __shared__ float sm[];
    float* SIN  = sm;
    float* HID  = sm;
    float* MSG  = sm + 16896;
    float* WS   = sm + 37376;
    float* RIJ  = sm + 41472;
    float* CW2s = sm + 43008;

    const int tid = threadIdx.x;
    const int el = tid >> 1, p = tid & 1;
    const int e = blockIdx.x * 128 + el;
    const int r = erow[e], c = ecol[e];

    // gather: s_in smem row = [h_row(128)|h_col(128)|ef(8)|scalar(3)|pad->0]
    {
        const float4* hr = (const float4*)(hN + (size_t)r * 128);
        const float4* hc = (const float4*)(hN + (size_t)c * 128);
        float* sr = SIN + el * 292;
#pragma unroll
        for (int j = 0; j < 16; j++) *(float4*)(sr + (p * 16 + j) * 4) = hr[p * 16 + j];
#pragma unroll
        for (int j = 0; j < 16; j++) *(float4*)(sr + 128 + (p * 16 + j) * 4) = hc[p * 16 + j];
        if (p == 0) {
            const float4* ef = (const float4*)(efea + (size_t)e * 8);
            *(float4*)(sr + 256) = ef[0];
            *(float4*)(sr + 260) = ef[1];
            sr[267] = 0.0f;
#pragma unroll
            for (int j = 268; j < 292; j += 4) *(float4*)(sr + j) = make_float4(0.f, 0.f, 0.f, 0.f);
        } else {
            const float* eq_r = equ + (size_t)r * 9;
            const float* eq_c = equ + (size_t)c * 9;
            float* rj = RIJ + el * 12;
            float s0 = 0.f, s1 = 0.f, s2 = 0.f;
#pragma unroll
            for (int d = 0; d < 3; d++) {
                float v0 = eq_r[d * 3 + 0] - eq_c[d * 3 + 0];
                float v1 = eq_r[d * 3 + 1] - eq_c[d * 3 + 1];
                float v2 = eq_r[d * 3 + 2] - eq_c[d * 3 + 2];
                rj[d * 3 + 0] = v0; rj[d * 3 + 1] = v1; rj[d * 3 + 2] = v2;
                s0 += v0 * v0; s1 += v1 * v1; s2 += v2 * v2;
            }
            sr[264] = sqrtf(s0); sr[265] = sqrtf(s1); sr[266] = sqrtf(s2);
        }
    }

    const int tx = tid & 15, ty = tid >> 4;
    const int wk = tid >> 3, wc = (tid & 7) * 16;
    ull acc[8][4];
#pragma unroll
    for (int i = 0; i < 8; i++)
#pragma unroll
        for (int j = 0; j < 4; j++) acc[i][j] = 0ull;

    // message MLP
    gemm_t<8, 288, true>(SIN + ty * 8 * 292, 292, W1, 267, WS, tx, wk, wc, acc);
    __syncthreads();
    store_act<8, true>(acc, B1, HID, 132, tx, ty);
    gemm_t<8, 128, false>(HID + ty * 8 * 132, 132, W2, 128, WS, tx, wk, wc, acc);
    __syncthreads();
    store_act<8, true>(acc, B2, MSG, 132, tx, ty);

    // coord MLP layer 1
    gemm_t<8, 128, false>(MSG + ty * 8 * 132, 132, CW1, 128, WS, tx, wk, wc, acc);
    __syncthreads();
    store_act<8, true>(acc, CB1, HID, 132, tx, ty);
    if (tid < 128) CW2s[tid] = CW2[tid];
    __syncthreads();

    // coord scalar (2 threads/edge)
    float partial = 0.f;
    {
        const float* chrow = HID + el * 132 + p * 64;
        const float* wv = CW2s + p * 64;
#pragma unroll 8
        for (int j = 0; j < 64; j++) partial += chrow[j] * wv[j];
    }
    partial += __shfl_xor_sync(0xffffffffu, partial, 1);
    float cms = partial + CB2[0];

    // scatter
    if (p == 0) {
        const float* rj = RIJ + el * 12;
        float* fs = fsum + (size_t)r * 12;
#pragma unroll
        for (int i = 0; i < 9; i++) atomicAdd(fs + i, rj[i] * cms);
    }
    {
        const float* mg = MSG + el * 132 + p * 64;
        float* ms = msum + (size_t)r * 128 + p * 64;
#pragma unroll 8
        for (int i = 0; i < 64; i++) atomicAdd(ms + i, mg[i]);
    }
}

// ---------------- node kernel: 64 nodes / block ----------------
// smem floats: CAT[64][260]@0 (16640) ; WS@16640 (4096) ; HG[64][132]@20736 (8448) ; QW2s@29184 (128)
#define N_SMEM_FLOATS 29312
#define N_SMEM_BYTES (N_SMEM_FLOATS * 4)

__global__ __launch_bounds__(256, 1)
void node_kernel(const float* __restrict__ hN, const float* __restrict__ equ_in,
                 const float* __restrict__ fsum, const float* __restrict__ msum,
                 const float* __restrict__ cnt,
                 const float* __restrict__ NW1, const float* __restrict__ NB1,
                 const float* __restrict__ NW2, const float* __restrict__ NB2,
                 const float* __restrict__ QW1, const float* __restrict__ QB1,
                 const float* __restrict__ QW2, const float* __restrict__ QB2,
                 float* __restrict__ equ_out, float* __restrict__ h_out, int N)
{
    extern __shared__ float sm[];
    float* CAT = sm;
    float* WS  = sm + 16640;
    float* HG  = sm + 20736;
    float* QW2s = sm + 29184;

    const int tid = threadIdx.x;
    const int l = tid >> 2, p = tid & 3;
    const int n0 = blockIdx.x * 64;
    const int n = n0 + l;

    {
        float* cr = CAT + l * 260;
        if (n < N) {
            const float4* hp = (const float4*)(hN + (size_t)n * 128);
            const float4* mp = (const float4*)(msum + (size_t)n * 128);
#pragma unroll
            for (int j = 0; j < 8; j++) {
                *(float4*)(cr + (p * 8 + j) * 4) = hp[p * 8 + j];
                *(float4*)(cr + 128 + (p * 8 + j) * 4) = mp[p * 8 + j];
            }
        } else {
#pragma unroll
            for (int j = 0; j < 8; j++) {
                *(float4*)(cr + (p * 8 + j) * 4) = make_float4(0.f, 0.f, 0.f, 0.f);
                *(float4*)(cr + 128 + (p * 8 + j) * 4) = make_float4(0.f, 0.f, 0.f, 0.f);
            }
        }
    }
    if (tid < 128) QW2s[tid] = QW2[tid];

    const int tx = tid & 15, ty = tid >> 4;
    const int wk = tid >> 3, wc = (tid & 7) * 16;
    ull acc[4][4];
#pragma unroll
    for (int i = 0; i < 4; i++)
#pragma unroll
        for (int j = 0; j < 4; j++) acc[i][j] = 0ull;

    // gate MLP hidden
    gemm_t<4, 128, false>(CAT + ty * 4 * 260, 260, QW1, 128, WS, tx, wk, wc, acc);
    __syncthreads();
    store_act<4, true>(acc, QB1, HG, 132, tx, ty);
    __syncthreads();

    float partial = 0.f;
    {
        const float* gh = HG + l * 132 + p * 32;
        const float* gw = QW2s + p * 32;
#pragma unroll 8
        for (int j = 0; j < 32; j++) partial += gh[j] * gw[j];
    }
    partial += __shfl_xor_sync(0xffffffffu, partial, 1);
    partial += __shfl_xor_sync(0xffffffffu, partial, 2);
    float gate = partial + QB2[0];

    if (p == 0 && n < N) {
        float invc = 1.0f / fmaxf(cnt[n], 1.0f);
        const float* fi = fsum + (size_t)n * 12;
        const float* ei = equ_in + (size_t)n * 9;
        float* eo = equ_out + (size_t)n * 9;
#pragma unroll
        for (int i = 0; i < 9; i++) {
            float tf = fi[i] * invc;
            tf = fminf(fmaxf(tf, -100.f), 100.f);
            eo[i] = gate * ei[i] + tf;
        }
    }

    // node MLP
    gemm_t<4, 256, false>(CAT + ty * 4 * 260, 260, NW1, 256, WS, tx, wk, wc, acc);
    __syncthreads();
    store_act<4, true>(acc, NB1, HG, 132, tx, ty);
    gemm_t<4, 128, false>(HG + ty * 4 * 132, 132, NW2, 128, WS, tx, wk, wc, acc);
    {
        float bs[8];
        *(float4*)&bs[0] = *(const float4*)(NB2 + tx * 8);
        *(float4*)&bs[4] = *(const float4*)(NB2 + tx * 8 + 4);
#pragma unroll
        for (int rr = 0; rr < 4; rr++) {
            int nn = n0 + ty * 4 + rr;
            if (nn < N) {
                float v[8];
#pragma unroll
                for (int cp = 0; cp < 4; cp++) {
                    float x0, x1; unpack2(acc[rr][cp], x0, x1);
                    v[2 * cp] = x0 + bs[2 * cp];
                    v[2 * cp + 1] = x1 + bs[2 * cp + 1];
                }
                float* op = h_out + (size_t)nn * 128 + tx * 8;
                *(float4*)(op) = make_float4(v[0], v[1], v[2], v[3]);
                *(float4*)(op + 4) = make_float4(v[4], v[5], v[6], v[7]);
            }
        }
    }
}

__global__ void embed_kernel(const float* __restrict__ h, const float* __restrict__ W,
                             const float* __restrict__ b, float* __restrict__ out)
{
    __shared__ float hs[16];
    int n = blockIdx.x, c = threadIdx.x;
    if (c < 16) hs[c] = h[n * 16 + c];
    __syncthreads();
    float a = b[c];
#pragma unroll
    for (int k = 0; k < 16; k++) a += hs[k] * W[k * 128 + c];
    out[(size_t)n * 128 + c] = a;
}

__global__ void deg_kernel(const int* __restrict__ erow, float* __restrict__ cnt)
{
    int e = blockIdx.x * 256 + threadIdx.x;
    if (e < EE) atomicAdd(cnt + erow[e], 1.0f);
}

extern "C" void kernel_launch(void* const* d_in, const int* in_sizes, int n_in,
                              void* d_out, int out_size)
{
    (void)in_sizes; (void)n_in; (void)out_size;
    const float* equ   = (const float*)d_in[0];
    const float* h_in  = (const float*)d_in[1];
    const float* efea  = (const float*)d_in[2];
    const float* embW  = (const float*)d_in[3];
    const float* embB  = (const float*)d_in[4];
    const float* msgW1 = (const float*)d_in[5];
    const float* msgB1 = (const float*)d_in[6];
    const float* msgW2 = (const float*)d_in[7];
    const float* msgB2 = (const float*)d_in[8];
    const float* cW1   = (const float*)d_in[9];
    const float* cB1   = (const float*)d_in[10];
    const float* cW2   = (const float*)d_in[11];
    const float* cB2   = (const float*)d_in[12];
    const float* nW1   = (const float*)d_in[13];
    const float* nB1   = (const float*)d_in[14];
    const float* nW2   = (const float*)d_in[15];
    const float* nB2   = (const float*)d_in[16];
    const float* qW1   = (const float*)d_in[17];
    const float* qB1   = (const float*)d_in[18];
    const float* qW2   = (const float*)d_in[19];
    const float* qB2   = (const float*)d_in[20];
    const int*   eidx  = (const int*)d_in[21];
    const int* erow = eidx;
    const int* ecol = eidx + EE;
    float* out = (float*)d_out;

    cudaFuncSetAttribute(edge_kernel, cudaFuncAttributeMaxDynamicSharedMemorySize, E_SMEM_BYTES);
    cudaFuncSetAttribute(node_kernel, cudaFuncAttributeMaxDynamicSharedMemorySize, N_SMEM_BYTES);

    float *p_h0, *p_h1, *p_equ1, *p_fsum, *p_msum, *p_cnt;
    cudaGetSymbolAddress((void**)&p_h0, g_h0);
    cudaGetSymbolAddress((void**)&p_h1, g_h1);
    cudaGetSymbolAddress((void**)&p_equ1, g_equ1);
    cudaGetSymbolAddress((void**)&p_fsum, g_fsum);
    cudaGetSymbolAddress((void**)&p_msum, g_msum);
    cudaGetSymbolAddress((void**)&p_cnt, g_cnt);

    cudaMemsetAsync(p_cnt, 0, NN * sizeof(float));
    deg_kernel<<<(EE + 255) / 256, 256>>>(erow, p_cnt);
    embed_kernel<<<NN, 128>>>(h_in, embW, embB, p_h0);

    const int nblk = (NN + 63) / 64;

    for (int i = 0; i < 2; i++) {
        const float* h_cur   = (i == 0) ? p_h0 : p_h1;
        const float* equ_cur = (i == 0) ? equ : p_equ1;
        float* equ_nxt = (i == 0) ? p_equ1 : out;
        float* h_nxt   = (i == 0) ? p_h1 : (out + NN * 9);

        cudaMemsetAsync(p_fsum, 0, NN * 12 * sizeof(float));
        cudaMemsetAsync(p_msum, 0, (size_t)NN * HH * sizeof(float));

        edge_kernel<<<EE / 128, 256, E_SMEM_BYTES>>>(
            equ_cur, h_cur, efea, erow, ecol,
            msgW1 + (size_t)i * 267 * 128, msgB1 + i * 128,
            msgW2 + (size_t)i * 128 * 128, msgB2 + i * 128,
            cW1 + (size_t)i * 128 * 128, cB1 + i * 128,
            cW2 + (size_t)i * 128, cB2 + i,
            p_fsum, p_msum);

        node_kernel<<<nblk, 256, N_SMEM_BYTES>>>(
            h_cur, equ_cur, p_fsum, p_msum, p_cnt,
            nW1 + (size_t)i * 256 * 128, nB1 + i * 128,
            nW2 + (size_t)i * 128 * 128, nB2 + i * 128,
            qW1 + (size_t)i * 128 * 128, qB1 + i * 128,
            qW2 + (size_t)i * 128, qB2 + i,
            equ_nxt, h_nxt, NN);
    }
}

// round 4
// speedup vs baseline: 1.1342x; 1.1342x over previous
#include <cuda_runtime.h>
#include <math.h>

typedef unsigned long long ull;

#define NN 20000
#define EE 640000
#define HH 128

__device__ __forceinline__ ull pack2(float x, float y) {
    ull r; asm("mov.b64 %0, {%1, %2};" : "=l"(r) : "f"(x), "f"(y)); return r;
}
__device__ __forceinline__ void unpack2(ull v, float& x, float& y) {
    asm("mov.b64 {%0, %1}, %2;" : "=f"(x), "=f"(y) : "l"(v));
}
__device__ __forceinline__ void fma2(ull& d, ull a, ull b) {
    asm("fma.rn.f32x2 %0, %1, %2, %0;" : "+l"(d) : "l"(a), "l"(b));
}
__device__ __forceinline__ float silu_f(float x) { return x / (1.0f + expf(-x)); }

// ---------------- scratch ----------------
__device__ float g_h0[NN * HH];
__device__ float g_h1[NN * HH];
__device__ float g_equ1[NN * 9];
__device__ float g_fsum[NN * 12];
__device__ float g_msum[NN * HH];
__device__ float g_cnt[NN];
__device__ float g_Pr[NN * HH];
__device__ float g_Pc[NN * HH];

// ---------------- tiled GEMM (256 thr, ROWSx8 micro-tile, f32x2) ----------------
template<int ROWS, int KPAD>
__device__ __forceinline__ void gemm_t(const float* As, int lda,
                                       const float* __restrict__ Wg,
                                       float* WS, int tx, int wk, int wc,
                                       ull (&acc)[ROWS][4])
{
#pragma unroll 1
    for (int kc = 0; kc < KPAD; kc += 32) {
        int gk = kc + wk;
        const float4* wp = (const float4*)(Wg + (size_t)gk * 128 + wc);
        float4 v0 = wp[0], v1 = wp[1], v2 = wp[2], v3 = wp[3];
        __syncthreads();
        float4* wsp = (float4*)(WS + wk * 128 + wc);
        wsp[0] = v0; wsp[1] = v1; wsp[2] = v2; wsp[3] = v3;
        __syncthreads();
        const float* Arow = As + kc;
        const float* Bcol = WS + tx * 8;
#pragma unroll 4
        for (int kk = 0; kk < 32; kk++) {
            ull b0 = *(const ull*)(Bcol + kk * 128 + 0);
            ull b1 = *(const ull*)(Bcol + kk * 128 + 2);
            ull b2 = *(const ull*)(Bcol + kk * 128 + 4);
            ull b3 = *(const ull*)(Bcol + kk * 128 + 6);
#pragma unroll
            for (int rr = 0; rr < ROWS; rr++) {
                float a = Arow[rr * lda + kk];
                ull ap = pack2(a, a);
                fma2(acc[rr][0], ap, b0);
                fma2(acc[rr][1], ap, b1);
                fma2(acc[rr][2], ap, b2);
                fma2(acc[rr][3], ap, b3);
            }
        }
    }
}

template<int ROWS, bool SILU>
__device__ __forceinline__ void store_act(ull (&acc)[ROWS][4],
                                          const float* __restrict__ bias,
                                          float* dst, int ldd, int tx, int ty)
{
    float bs[8];
    *(float4*)&bs[0] = *(const float4*)(bias + tx * 8);
    *(float4*)&bs[4] = *(const float4*)(bias + tx * 8 + 4);
#pragma unroll
    for (int rr = 0; rr < ROWS; rr++) {
        float* orow = dst + (ty * ROWS + rr) * ldd + tx * 8;
#pragma unroll
        for (int cp = 0; cp < 4; cp++) {
            float x0, x1; unpack2(acc[rr][cp], x0, x1);
            x0 += bs[2 * cp]; x1 += bs[2 * cp + 1];
            if (SILU) { x0 = silu_f(x0); x1 = silu_f(x1); }
            *(float2*)(orow + 2 * cp) = make_float2(x0, x1);
            acc[rr][cp] = 0ull;
        }
    }
}

// global store with optional bias, no act; zeroes acc
template<int ROWS>
__device__ __forceinline__ void store_glob(ull (&acc)[ROWS][4], const float* bias,
                                           float* out, int n0, int tx, int ty, int N)
{
    float bs[8];
    if (bias) {
        *(float4*)&bs[0] = *(const float4*)(bias + tx * 8);
        *(float4*)&bs[4] = *(const float4*)(bias + tx * 8 + 4);
    } else {
#pragma unroll
        for (int j = 0; j < 8; j++) bs[j] = 0.f;
    }
#pragma unroll
    for (int rr = 0; rr < ROWS; rr++) {
        int nn = n0 + ty * ROWS + rr;
#pragma unroll
        for (int cp = 0; cp < 4; cp++) {
            float x0, x1; unpack2(acc[rr][cp], x0, x1);
            if (nn < N)
                *(float2*)(out + (size_t)nn * 128 + tx * 8 + 2 * cp) =
                    make_float2(x0 + bs[2 * cp], x1 + bs[2 * cp + 1]);
            acc[rr][cp] = 0ull;
        }
    }
}

// ---------------- prep: Pr = h@W1[3:131]+b1, Pc = h@W1[131:259] ----------------
#define P_SMEM_BYTES (12544 * 4)
__global__ __launch_bounds__(256, 2)
void prep_kernel(const float* __restrict__ hN, const float* __restrict__ W1,
                 const float* __restrict__ B1,
                 float* __restrict__ Pr, float* __restrict__ Pc, int N)
{
    extern __shared__ float sm[];
    float* A = sm;            // [64][132]
    float* WS = sm + 8448;    // [32][128]
    const int tid = threadIdx.x;
    const int l = tid >> 2, p = tid & 3;
    const int n0 = blockIdx.x * 64;
    const int n = n0 + l;
    {
        float* ar = A + l * 132 + p * 32;
        if (n < N) {
            const float4* hp = (const float4*)(hN + (size_t)n * 128 + p * 32);
#pragma unroll
            for (int j = 0; j < 8; j++) *(float4*)(ar + j * 4) = hp[j];
        } else {
#pragma unroll
            for (int j = 0; j < 8; j++) *(float4*)(ar + j * 4) = make_float4(0.f, 0.f, 0.f, 0.f);
        }
    }
    const int tx = tid & 15, ty = tid >> 4;
    const int wk = tid >> 3, wc = (tid & 7) * 16;
    ull acc[4][4];
#pragma unroll
    for (int i = 0; i < 4; i++)
#pragma unroll
        for (int j = 0; j < 4; j++) acc[i][j] = 0ull;

    gemm_t<4, 128>(A + ty * 4 * 132, 132, W1 + 3 * 128, WS, tx, wk, wc, acc);
    store_glob<4>(acc, B1, Pr, n0, tx, ty, N);
    gemm_t<4, 128>(A + ty * 4 * 132, 132, W1 + 131 * 128, WS, tx, wk, wc, acc);
    store_glob<4>(acc, (const float*)0, Pc, n0, tx, ty, N);
}

// ---------------- edge kernel: 64 edges / block ----------------
// floats: HID[64][132]@0 ; MSG@8448 ; WS@16896 ; RIJ[64][12]@20992 ; SCAL[64][12]@21760 ; W1SE[11][128]@22528
#define E_SMEM_FLOATS 23936
#define E_SMEM_BYTES (E_SMEM_FLOATS * 4)

__global__ __launch_bounds__(256, 2)
void edge_kernel(const float* __restrict__ equ,
                 const float* __restrict__ Pr, const float* __restrict__ Pc,
                 const float* __restrict__ efea,
                 const int* __restrict__ erow, const int* __restrict__ ecol,
                 const float* __restrict__ W1,
                 const float* __restrict__ W2, const float* __restrict__ B2,
                 const float* __restrict__ CW1, const float* __restrict__ CB1,
                 const float* __restrict__ CW2, const float* __restrict__ CB2,
                 float* __restrict__ fsum, float* __restrict__ msum)
{
    extern __shared__ float sm[];
    float* HID  = sm;
    float* MSG  = sm + 8448;
    float* WS   = sm + 16896;
    float* RIJ  = sm + 20992;
    float* SCAL = sm + 21760;
    float* W1SE = sm + 22528;

    const int tid = threadIdx.x;
    const int el = tid >> 2, p = tid & 3;
    const int e = blockIdx.x * 64 + el;
    const int r = erow[e], c = ecol[e];

    // stage W1 scalar/ef rows: j<3 -> rows 0..2 ; j>=3 -> rows 259..266
    for (int idx = tid; idx < 11 * 128; idx += 256) {
        int row = idx >> 7, col = idx & 127;
        int grow = (row < 3) ? row : row + 256;
        W1SE[idx] = W1[grow * 128 + col];
    }
    if (p == 0) {
        const float* er_ = equ + (size_t)r * 9;
        const float* ec_ = equ + (size_t)c * 9;
        float rij[9];
#pragma unroll
        for (int i = 0; i < 9; i++) { rij[i] = er_[i] - ec_[i]; RIJ[el * 12 + i] = rij[i]; }
#pragma unroll
        for (int k = 0; k < 3; k++)
            SCAL[el * 12 + k] = sqrtf(rij[k] * rij[k] + rij[3 + k] * rij[3 + k] + rij[6 + k] * rij[6 + k]);
    } else if (p == 1) {
        const float4* ef = (const float4*)(efea + (size_t)e * 8);
        float4 a = ef[0], b = ef[1];
        SCAL[el * 12 + 3] = a.x; SCAL[el * 12 + 4] = a.y; SCAL[el * 12 + 5] = a.z; SCAL[el * 12 + 6] = a.w;
        SCAL[el * 12 + 7] = b.x; SCAL[el * 12 + 8] = b.y; SCAL[el * 12 + 9] = b.z; SCAL[el * 12 + 10] = b.w;
    }
    __syncthreads();

    // hidden = silu(Pr[r] + Pc[c] + s . W1se)   (32 cols per thread)
    {
        float s[11];
#pragma unroll
        for (int j = 0; j < 11; j++) s[j] = SCAL[el * 12 + j];
        const float4* pr = (const float4*)(Pr + (size_t)r * 128 + p * 32);
        const float4* pc = (const float4*)(Pc + (size_t)c * 128 + p * 32);
        float* hrow = HID + el * 132 + p * 32;
#pragma unroll
        for (int cg = 0; cg < 8; cg++) {
            float4 a = pr[cg], b = pc[cg];
            float4 v = make_float4(a.x + b.x, a.y + b.y, a.z + b.z, a.w + b.w);
#pragma unroll
            for (int j = 0; j < 11; j++) {
                float4 w = *(const float4*)(W1SE + j * 128 + p * 32 + cg * 4);
                v.x += s[j] * w.x; v.y += s[j] * w.y; v.z += s[j] * w.z; v.w += s[j] * w.w;
            }
            *(float4*)(hrow + cg * 4) = make_float4(silu_f(v.x), silu_f(v.y), silu_f(v.z), silu_f(v.w));
        }
    }

    const int tx = tid & 15, ty = tid >> 4;
    const int wk = tid >> 3, wc = (tid & 7) * 16;
    ull acc[4][4];
#pragma unroll
    for (int i = 0; i < 4; i++)
#pragma unroll
        for (int j = 0; j < 4; j++) acc[i][j] = 0ull;

    // message = silu(hidden @ W2 + b2)
    gemm_t<4, 128>(HID + ty * 4 * 132, 132, W2, WS, tx, wk, wc, acc);
    store_act<4, true>(acc, B2, MSG, 132, tx, ty);
    // ch = silu(message @ CW1 + cb1) -> HID
    gemm_t<4, 128>(MSG + ty * 4 * 132, 132, CW1, WS, tx, wk, wc, acc);
    __syncthreads();                 // gemm readers of HID must finish before overwrite
    store_act<4, true>(acc, CB1, HID, 132, tx, ty);
    __syncthreads();

    // cms = ch . CW2 + cb2   (4 threads/edge)
    float partial = 0.f;
    {
        const float* chrow = HID + el * 132 + p * 32;
        const float* wv = CW2 + p * 32;
#pragma unroll 8
        for (int j = 0; j < 32; j++) partial += chrow[j] * wv[j];
    }
    partial += __shfl_xor_sync(0xffffffffu, partial, 1);
    partial += __shfl_xor_sync(0xffffffffu, partial, 2);
    float cms = partial + CB2[0];

    // scatter
    if (p == 0) {
        const float* rj = RIJ + el * 12;
        float* fs = fsum + (size_t)r * 12;
#pragma unroll
        for (int i = 0; i < 9; i++) atomicAdd(fs + i, rj[i] * cms);
    }
    {
        const float* mg = MSG + el * 132 + p * 32;
        float* ms = msum + (size_t)r * 128 + p * 32;
#pragma unroll 8
        for (int i = 0; i < 32; i++) atomicAdd(ms + i, mg[i]);
    }
}

// ---------------- node kernel: 64 nodes / block ----------------
#define N_SMEM_FLOATS 29312
#define N_SMEM_BYTES (N_SMEM_FLOATS * 4)

__global__ __launch_bounds__(256, 1)
void node_kernel(const float* __restrict__ hN, const float* __restrict__ equ_in,
                 const float* __restrict__ fsum, const float* __restrict__ msum,
                 const float* __restrict__ cnt,
                 const float* __restrict__ NW1, const float* __restrict__ NB1,
                 const float* __restrict__ NW2, const float* __restrict__ NB2,
                 const float* __restrict__ QW1, const float* __restrict__ QB1,
                 const float* __restrict__ QW2, const float* __restrict__ QB2,
                 float* __restrict__ equ_out, float* __restrict__ h_out, int N)
{
    extern __shared__ float sm[];
    float* CAT = sm;            // [64][260]
    float* WS  = sm + 16640;
    float* HG  = sm + 20736;    // [64][132]
    float* QW2s = sm + 29184;

    const int tid = threadIdx.x;
    const int l = tid >> 2, p = tid & 3;
    const int n0 = blockIdx.x * 64;
    const int n = n0 + l;
    {
        float* cr = CAT + l * 260;
        if (n < N) {
            const float4* hp = (const float4*)(hN + (size_t)n * 128);
            const float4* mp = (const float4*)(msum + (size_t)n * 128);
#pragma unroll
            for (int j = 0; j < 8; j++) {
                *(float4*)(cr + (p * 8 + j) * 4) = hp[p * 8 + j];
                *(float4*)(cr + 128 + (p * 8 + j) * 4) = mp[p * 8 + j];
            }
        } else {
#pragma unroll
            for (int j = 0; j < 8; j++) {
                *(float4*)(cr + (p * 8 + j) * 4) = make_float4(0.f, 0.f, 0.f, 0.f);
                *(float4*)(cr + 128 + (p * 8 + j) * 4) = make_float4(0.f, 0.f, 0.f, 0.f);
            }
        }
    }
    if (tid < 128) QW2s[tid] = QW2[tid];

    const int tx = tid & 15, ty = tid >> 4;
    const int wk = tid >> 3, wc = (tid & 7) * 16;
    ull acc[4][4];
#pragma unroll
    for (int i = 0; i < 4; i++)
#pragma unroll
        for (int j = 0; j < 4; j++) acc[i][j] = 0ull;

    gemm_t<4, 128>(CAT + ty * 4 * 260, 260, QW1, WS, tx, wk, wc, acc);
    __syncthreads();
    store_act<4, true>(acc, QB1, HG, 132, tx, ty);
    __syncthreads();

    float partial = 0.f;
    {
        const float* gh = HG + l * 132 + p * 32;
        const float* gw = QW2s + p * 32;
#pragma unroll 8
        for (int j = 0; j < 32; j++) partial += gh[j] * gw[j];
    }
    partial += __shfl_xor_sync(0xffffffffu, partial, 1);
    partial += __shfl_xor_sync(0xffffffffu, partial, 2);
    float gate = partial + QB2[0];

    if (p == 0 && n < N) {
        float invc = 1.0f / fmaxf(cnt[n], 1.0f);
        const float* fi = fsum + (size_t)n * 12;
        const float* ei = equ_in + (size_t)n * 9;
        float* eo = equ_out + (size_t)n * 9;
#pragma unroll
        for (int i = 0; i < 9; i++) {
            float tf = fi[i] * invc;
            tf = fminf(fmaxf(tf, -100.f), 100.f);
            eo[i] = gate * ei[i] + tf;
        }
    }

    // h_out = silu(cat @ NW1 + nb1) @ NW2 + nb2
    gemm_t<4, 256>(CAT + ty * 4 * 260, 260, NW1, WS, tx, wk, wc, acc);
    __syncthreads();
    store_act<4, true>(acc, NB1, HG, 132, tx, ty);
    gemm_t<4, 128>(HG + ty * 4 * 132, 132, NW2, WS, tx, wk, wc, acc);
    {
        float bs[8];
        *(float4*)&bs[0] = *(const float4*)(NB2 + tx * 8);
        *(float4*)&bs[4] = *(const float4*)(NB2 + tx * 8 + 4);
#pragma unroll
        for (int rr = 0; rr < 4; rr++) {
            int nn = n0 + ty * 4 + rr;
            if (nn < N) {
                float* op = h_out + (size_t)nn * 128 + tx * 8;
#pragma unroll
                for (int cp = 0; cp < 4; cp++) {
                    float x0, x1; unpack2(acc[rr][cp], x0, x1);
                    *(float2*)(op + 2 * cp) = make_float2(x0 + bs[2 * cp], x1 + bs[2 * cp + 1]);
                }
            }
        }
    }
}

__global__ void embed_kernel(const float* __restrict__ h, const float* __restrict__ W,
                             const float* __restrict__ b, float* __restrict__ out)
{
    __shared__ float hs[16];
    int n = blockIdx.x, c = threadIdx.x;
    if (c < 16) hs[c] = h[n * 16 + c];
    __syncthreads();
    float a = b[c];
#pragma unroll
    for (int k = 0; k < 16; k++) a += hs[k] * W[k * 128 + c];
    out[(size_t)n * 128 + c] = a;
}

__global__ void deg_kernel(const int* __restrict__ erow, float* __restrict__ cnt)
{
    int e = blockIdx.x * 256 + threadIdx.x;
    if (e < EE) atomicAdd(cnt + erow[e], 1.0f);
}

extern "C" void kernel_launch(void* const* d_in, const int* in_sizes, int n_in,
                              void* d_out, int out_size)
{
    (void)in_sizes; (void)n_in; (void)out_size;
    const float* equ   = (const float*)d_in[0];
    const float* h_in  = (const float*)d_in[1];
    const float* efea  = (const float*)d_in[2];
    const float* embW  = (const float*)d_in[3];
    const float* embB  = (const float*)d_in[4];
    const float* msgW1 = (const float*)d_in[5];
    const float* msgB1 = (const float*)d_in[6];
    const float* msgW2 = (const float*)d_in[7];
    const float* msgB2 = (const float*)d_in[8];
    const float* cW1   = (const float*)d_in[9];
    const float* cB1   = (const float*)d_in[10];
    const float* cW2   = (const float*)d_in[11];
    const float* cB2   = (const float*)d_in[12];
    const float* nW1   = (const float*)d_in[13];
    const float* nB1   = (const float*)d_in[14];
    const float* nW2   = (const float*)d_in[15];
    const float* nB2   = (const float*)d_in[16];
    const float* qW1   = (const float*)d_in[17];
    const float* qB1   = (const float*)d_in[18];
    const float* qW2   = (const float*)d_in[19];
    const float* qB2   = (const float*)d_in[20];
    const int*   eidx  = (const int*)d_in[21];
    const int* erow = eidx;
    const int* ecol = eidx + EE;
    float* out = (float*)d_out;

    cudaFuncSetAttribute(edge_kernel, cudaFuncAttributeMaxDynamicSharedMemorySize, E_SMEM_BYTES);
    cudaFuncSetAttribute(node_kernel, cudaFuncAttributeMaxDynamicSharedMemorySize, N_SMEM_BYTES);
    cudaFuncSetAttribute(prep_kernel, cudaFuncAttributeMaxDynamicSharedMemorySize, P_SMEM_BYTES);

    float *p_h0, *p_h1, *p_equ1, *p_fsum, *p_msum, *p_cnt, *p_Pr, *p_Pc;
    cudaGetSymbolAddress((void**)&p_h0, g_h0);
    cudaGetSymbolAddress((void**)&p_h1, g_h1);
    cudaGetSymbolAddress((void**)&p_equ1, g_equ1);
    cudaGetSymbolAddress((void**)&p_fsum, g_fsum);
    cudaGetSymbolAddress((void**)&p_msum, g_msum);
    cudaGetSymbolAddress((void**)&p_cnt, g_cnt);
    cudaGetSymbolAddress((void**)&p_Pr, g_Pr);
    cudaGetSymbolAddress((void**)&p_Pc, g_Pc);

    cudaMemsetAsync(p_cnt, 0, NN * sizeof(float));
    deg_kernel<<<(EE + 255) / 256, 256>>>(erow, p_cnt);
    embed_kernel<<<NN, 128>>>(h_in, embW, embB, p_h0);

    const int nblk = (NN + 63) / 64;

    for (int i = 0; i < 2; i++) {
        const float* h_cur   = (i == 0) ? p_h0 : p_h1;
        const float* equ_cur = (i == 0) ? equ : p_equ1;
        float* equ_nxt = (i == 0) ? p_equ1 : out;
        float* h_nxt   = (i == 0) ? p_h1 : (out + NN * 9);

        cudaMemsetAsync(p_fsum, 0, NN * 12 * sizeof(float));
        cudaMemsetAsync(p_msum, 0, (size_t)NN * HH * sizeof(float));

        prep_kernel<<<nblk, 256, P_SMEM_BYTES>>>(
            h_cur, msgW1 + (size_t)i * 267 * 128, msgB1 + i * 128, p_Pr, p_Pc, NN);

        edge_kernel<<<EE / 64, 256, E_SMEM_BYTES>>>(
            equ_cur, p_Pr, p_Pc, efea, erow, ecol,
            msgW1 + (size_t)i * 267 * 128,
            msgW2 + (size_t)i * 128 * 128, msgB2 + i * 128,
            cW1 + (size_t)i * 128 * 128, cB1 + i * 128,
            cW2 + (size_t)i * 128, cB2 + i,
            p_fsum, p_msum);

        node_kernel<<<nblk, 256, N_SMEM_BYTES>>>(
            h_cur, equ_cur, p_fsum, p_msum, p_cnt,
            nW1 + (size_t)i * 256 * 128, nB1 + i * 128,
            nW2 + (size_t)i * 128 * 128, nB2 + i * 128,
            qW1 + (size_t)i * 128 * 128, qB1 + i * 128,
            qW2 + (size_t)i * 128, qB2 + i,
            equ_nxt, h_nxt, NN);
    }
}

// round 5
// speedup vs baseline: 1.5039x; 1.3259x over previous
#include <cuda_runtime.h>
#include <math.h>

typedef unsigned long long ull;

#define NN 20000
#define EE 640000
#define HH 128

__device__ __forceinline__ ull pack2(float x, float y) {
    ull r; asm("mov.b64 %0, {%1, %2};" : "=l"(r) : "f"(x), "f"(y)); return r;
}
__device__ __forceinline__ void unpack2(ull v, float& x, float& y) {
    asm("mov.b64 {%0, %1}, %2;" : "=f"(x), "=f"(y) : "l"(v));
}
__device__ __forceinline__ void fma2(ull& d, ull a, ull b) {
    asm("fma.rn.f32x2 %0, %1, %2, %0;" : "+l"(d) : "l"(a), "l"(b));
}
__device__ __forceinline__ float silu_f(float x) { return x / (1.0f + expf(-x)); }

__device__ __forceinline__ void red4(float* p, float a, float b, float c, float d) {
    asm volatile("red.global.add.v4.f32 [%0], {%1, %2, %3, %4};"
                 :: "l"(p), "f"(a), "f"(b), "f"(c), "f"(d) : "memory");
}

// ---------------- scratch ----------------
__device__ float g_h0[NN * HH];
__device__ float g_h1[NN * HH];
__device__ float g_equ1[NN * 9];
__device__ float g_fsum[NN * 12];
__device__ float g_msum[NN * HH];
__device__ float g_cnt[NN];
__device__ float g_Pr[NN * HH];
__device__ float g_Pc[NN * HH];

// ---------------- tiled GEMM (256 thr, ROWSx8 micro-tile, f32x2) ----------------
// Conflict-free mapping: thread (tx,ty) owns column pairs {tx*2 + 32*cp}, cp=0..3.
// B LDS.64 per fetch: words tx*2,tx*2+1 over 16 tx -> all 32 banks once.
template<int ROWS, int KPAD>
__device__ __forceinline__ void gemm_t(const float* As, int lda,
                                       const float* __restrict__ Wg,
                                       float* WS, int tx, int wk, int wc,
                                       ull (&acc)[ROWS][4])
{
#pragma unroll 1
    for (int kc = 0; kc < KPAD; kc += 32) {
        int gk = kc + wk;
        const float4* wp = (const float4*)(Wg + (size_t)gk * 128 + wc);
        float4 v0 = wp[0], v1 = wp[1], v2 = wp[2], v3 = wp[3];
        __syncthreads();
        float4* wsp = (float4*)(WS + wk * 128 + wc);
        wsp[0] = v0; wsp[1] = v1; wsp[2] = v2; wsp[3] = v3;
        __syncthreads();
        const float* Arow = As + kc;
        const float* Bcol = WS + tx * 2;
#pragma unroll 4
        for (int kk = 0; kk < 32; kk++) {
            ull b0 = *(const ull*)(Bcol + kk * 128 + 0);
            ull b1 = *(const ull*)(Bcol + kk * 128 + 32);
            ull b2 = *(const ull*)(Bcol + kk * 128 + 64);
            ull b3 = *(const ull*)(Bcol + kk * 128 + 96);
#pragma unroll
            for (int rr = 0; rr < ROWS; rr++) {
                float a = Arow[rr * lda + kk];
                ull ap = pack2(a, a);
                fma2(acc[rr][0], ap, b0);
                fma2(acc[rr][1], ap, b1);
                fma2(acc[rr][2], ap, b2);
                fma2(acc[rr][3], ap, b3);
            }
        }
    }
}

template<int ROWS, bool SILU>
__device__ __forceinline__ void store_act(ull (&acc)[ROWS][4],
                                          const float* __restrict__ bias,
                                          float* dst, int ldd, int tx, int ty)
{
    float bs[8];
#pragma unroll
    for (int cp = 0; cp < 4; cp++) {
        float2 bb = *(const float2*)(bias + tx * 2 + 32 * cp);
        bs[2 * cp] = bb.x; bs[2 * cp + 1] = bb.y;
    }
#pragma unroll
    for (int rr = 0; rr < ROWS; rr++) {
        float* orow = dst + (ty * ROWS + rr) * ldd + tx * 2;
#pragma unroll
        for (int cp = 0; cp < 4; cp++) {
            float x0, x1; unpack2(acc[rr][cp], x0, x1);
            x0 += bs[2 * cp]; x1 += bs[2 * cp + 1];
            if (SILU) { x0 = silu_f(x0); x1 = silu_f(x1); }
            *(float2*)(orow + 32 * cp) = make_float2(x0, x1);
            acc[rr][cp] = 0ull;
        }
    }
}

template<int ROWS>
__device__ __forceinline__ void store_glob(ull (&acc)[ROWS][4], const float* bias,
                                           float* out, int n0, int tx, int ty, int N)
{
    float bs[8];
    if (bias) {
#pragma unroll
        for (int cp = 0; cp < 4; cp++) {
            float2 bb = *(const float2*)(bias + tx * 2 + 32 * cp);
            bs[2 * cp] = bb.x; bs[2 * cp + 1] = bb.y;
        }
    } else {
#pragma unroll
        for (int j = 0; j < 8; j++) bs[j] = 0.f;
    }
#pragma unroll
    for (int rr = 0; rr < ROWS; rr++) {
        int nn = n0 + ty * ROWS + rr;
#pragma unroll
        for (int cp = 0; cp < 4; cp++) {
            float x0, x1; unpack2(acc[rr][cp], x0, x1);
            if (nn < N)
                *(float2*)(out + (size_t)nn * 128 + tx * 2 + 32 * cp) =
                    make_float2(x0 + bs[2 * cp], x1 + bs[2 * cp + 1]);
            acc[rr][cp] = 0ull;
        }
    }
}

// ---------------- prep: Pr = h@W1[3:131]+b1, Pc = h@W1[131:259] ----------------
#define P_SMEM_BYTES (12544 * 4)
__global__ __launch_bounds__(256, 2)
void prep_kernel(const float* __restrict__ hN, const float* __restrict__ W1,
                 const float* __restrict__ B1,
                 float* __restrict__ Pr, float* __restrict__ Pc, int N)
{
    extern __shared__ float sm[];
    float* A = sm;            // [64][132]
    float* WS = sm + 8448;    // [32][128]
    const int tid = threadIdx.x;
    const int l = tid >> 2, p = tid & 3;
    const int n0 = blockIdx.x * 64;
    const int n = n0 + l;
    {
        float* ar = A + l * 132 + p * 32;
        if (n < N) {
            const float4* hp = (const float4*)(hN + (size_t)n * 128 + p * 32);
#pragma unroll
            for (int j = 0; j < 8; j++) *(float4*)(ar + j * 4) = hp[j];
        } else {
#pragma unroll
            for (int j = 0; j < 8; j++) *(float4*)(ar + j * 4) = make_float4(0.f, 0.f, 0.f, 0.f);
        }
    }
    const int tx = tid & 15, ty = tid >> 4;
    const int wk = tid >> 3, wc = (tid & 7) * 16;
    ull acc[4][4];
#pragma unroll
    for (int i = 0; i < 4; i++)
#pragma unroll
        for (int j = 0; j < 4; j++) acc[i][j] = 0ull;

    gemm_t<4, 128>(A + ty * 4 * 132, 132, W1 + 3 * 128, WS, tx, wk, wc, acc);
    store_glob<4>(acc, B1, Pr, n0, tx, ty, N);
    gemm_t<4, 128>(A + ty * 4 * 132, 132, W1 + 131 * 128, WS, tx, wk, wc, acc);
    store_glob<4>(acc, (const float*)0, Pc, n0, tx, ty, N);
}

// ---------------- edge kernel: 64 edges / block ----------------
// floats: HID[64][132]@0 ; MSG@8448 ; WS@16896 ; RIJ[64][12]@20992 ; SCAL[64][12]@21760 ; W1SE[11][128]@22528
#define E_SMEM_FLOATS 23936
#define E_SMEM_BYTES (E_SMEM_FLOATS * 4)

__global__ __launch_bounds__(256, 2)
void edge_kernel(const float* __restrict__ equ,
                 const float* __restrict__ Pr, const float* __restrict__ Pc,
                 const float* __restrict__ efea,
                 const int* __restrict__ erow, const int* __restrict__ ecol,
                 const float* __restrict__ W1,
                 const float* __restrict__ W2, const float* __restrict__ B2,
                 const float* __restrict__ CW1, const float* __restrict__ CB1,
                 const float* __restrict__ CW2, const float* __restrict__ CB2,
                 float* __restrict__ fsum, float* __restrict__ msum)
{
    extern __shared__ float sm[];
    float* HID  = sm;
    float* MSG  = sm + 8448;
    float* WS   = sm + 16896;
    float* RIJ  = sm + 20992;
    float* SCAL = sm + 21760;
    float* W1SE = sm + 22528;

    const int tid = threadIdx.x;
    const int el = tid >> 2, p = tid & 3;
    const int e = blockIdx.x * 64 + el;
    const int r = erow[e], c = ecol[e];

    for (int idx = tid; idx < 11 * 128; idx += 256) {
        int row = idx >> 7, col = idx & 127;
        int grow = (row < 3) ? row : row + 256;
        W1SE[idx] = W1[grow * 128 + col];
    }
    if (p == 0) {
        const float* er_ = equ + (size_t)r * 9;
        const float* ec_ = equ + (size_t)c * 9;
        float rij[9];
#pragma unroll
        for (int i = 0; i < 9; i++) { rij[i] = er_[i] - ec_[i]; RIJ[el * 12 + i] = rij[i]; }
#pragma unroll
        for (int k = 0; k < 3; k++)
            SCAL[el * 12 + k] = sqrtf(rij[k] * rij[k] + rij[3 + k] * rij[3 + k] + rij[6 + k] * rij[6 + k]);
    } else if (p == 1) {
        const float4* ef = (const float4*)(efea + (size_t)e * 8);
        float4 a = ef[0], b = ef[1];
        SCAL[el * 12 + 3] = a.x; SCAL[el * 12 + 4] = a.y; SCAL[el * 12 + 5] = a.z; SCAL[el * 12 + 6] = a.w;
        SCAL[el * 12 + 7] = b.x; SCAL[el * 12 + 8] = b.y; SCAL[el * 12 + 9] = b.z; SCAL[el * 12 + 10] = b.w;
    }
    __syncthreads();

    // hidden = silu(Pr[r] + Pc[c] + s . W1se)
    {
        float s[11];
#pragma unroll
        for (int j = 0; j < 11; j++) s[j] = SCAL[el * 12 + j];
        const float4* pr = (const float4*)(Pr + (size_t)r * 128 + p * 32);
        const float4* pc = (const float4*)(Pc + (size_t)c * 128 + p * 32);
        float* hrow = HID + el * 132 + p * 32;
#pragma unroll
        for (int cg = 0; cg < 8; cg++) {
            float4 a = pr[cg], b = pc[cg];
            float4 v = make_float4(a.x + b.x, a.y + b.y, a.z + b.z, a.w + b.w);
#pragma unroll
            for (int j = 0; j < 11; j++) {
                float4 w = *(const float4*)(W1SE + j * 128 + p * 32 + cg * 4);
                v.x += s[j] * w.x; v.y += s[j] * w.y; v.z += s[j] * w.z; v.w += s[j] * w.w;
            }
            *(float4*)(hrow + cg * 4) = make_float4(silu_f(v.x), silu_f(v.y), silu_f(v.z), silu_f(v.w));
        }
    }

    const int tx = tid & 15, ty = tid >> 4;
    const int wk = tid >> 3, wc = (tid & 7) * 16;
    ull acc[4][4];
#pragma unroll
    for (int i = 0; i < 4; i++)
#pragma unroll
        for (int j = 0; j < 4; j++) acc[i][j] = 0ull;

    // message = silu(hidden @ W2 + b2)
    gemm_t<4, 128>(HID + ty * 4 * 132, 132, W2, WS, tx, wk, wc, acc);
    store_act<4, true>(acc, B2, MSG, 132, tx, ty);
    // ch = silu(message @ CW1 + cb1) -> HID
    gemm_t<4, 128>(MSG + ty * 4 * 132, 132, CW1, WS, tx, wk, wc, acc);
    __syncthreads();
    store_act<4, true>(acc, CB1, HID, 132, tx, ty);
    __syncthreads();

    // cms = ch . CW2 + cb2
    float partial = 0.f;
    {
        const float* chrow = HID + el * 132 + p * 32;
        const float* wv = CW2 + p * 32;
#pragma unroll 8
        for (int j = 0; j < 32; j++) partial += chrow[j] * wv[j];
    }
    partial += __shfl_xor_sync(0xffffffffu, partial, 1);
    partial += __shfl_xor_sync(0xffffffffu, partial, 2);
    float cms = partial + CB2[0];

    // scatter (vectorized red)
    if (p == 0) {
        const float* rj = RIJ + el * 12;
        float* fs = fsum + (size_t)r * 12;
        red4(fs, rj[0] * cms, rj[1] * cms, rj[2] * cms, rj[3] * cms);
        red4(fs + 4, rj[4] * cms, rj[5] * cms, rj[6] * cms, rj[7] * cms);
        atomicAdd(fs + 8, rj[8] * cms);
    }
    {
        const float* mg = MSG + el * 132 + p * 32;
        float* ms = msum + (size_t)r * 128 + p * 32;
#pragma unroll
        for (int i = 0; i < 8; i++)
            red4(ms + i * 4, mg[i * 4], mg[i * 4 + 1], mg[i * 4 + 2], mg[i * 4 + 3]);
    }
}

// ---------------- node kernel: 64 nodes / block ----------------
#define N_SMEM_FLOATS 29312
#define N_SMEM_BYTES (N_SMEM_FLOATS * 4)

__global__ __launch_bounds__(256, 1)
void node_kernel(const float* __restrict__ hN, const float* __restrict__ equ_in,
                 const float* __restrict__ fsum, const float* __restrict__ msum,
                 const float* __restrict__ cnt,
                 const float* __restrict__ NW1, const float* __restrict__ NB1,
                 const float* __restrict__ NW2, const float* __restrict__ NB2,
                 const float* __restrict__ QW1, const float* __restrict__ QB1,
                 const float* __restrict__ QW2, const float* __restrict__ QB2,
                 float* __restrict__ equ_out, float* __restrict__ h_out, int N)
{
    extern __shared__ float sm[];
    float* CAT = sm;            // [64][260]
    float* WS  = sm + 16640;
    float* HG  = sm + 20736;    // [64][132]
    float* QW2s = sm + 29184;

    const int tid = threadIdx.x;
    const int l = tid >> 2, p = tid & 3;
    const int n0 = blockIdx.x * 64;
    const int n = n0 + l;
    {
        float* cr = CAT + l * 260;
        if (n < N) {
            const float4* hp = (const float4*)(hN + (size_t)n * 128);
            const float4* mp = (const float4*)(msum + (size_t)n * 128);
#pragma unroll
            for (int j = 0; j < 8; j++) {
                *(float4*)(cr + (p * 8 + j) * 4) = hp[p * 8 + j];
                *(float4*)(cr + 128 + (p * 8 + j) * 4) = mp[p * 8 + j];
            }
        } else {
#pragma unroll
            for (int j = 0; j < 8; j++) {
                *(float4*)(cr + (p * 8 + j) * 4) = make_float4(0.f, 0.f, 0.f, 0.f);
                *(float4*)(cr + 128 + (p * 8 + j) * 4) = make_float4(0.f, 0.f, 0.f, 0.f);
            }
        }
    }
    if (tid < 128) QW2s[tid] = QW2[tid];

    const int tx = tid & 15, ty = tid >> 4;
    const int wk = tid >> 3, wc = (tid & 7) * 16;
    ull acc[4][4];
#pragma unroll
    for (int i = 0; i < 4; i++)
#pragma unroll
        for (int j = 0; j < 4; j++) acc[i][j] = 0ull;

    gemm_t<4, 128>(CAT + ty * 4 * 260, 260, QW1, WS, tx, wk, wc, acc);
    __syncthreads();
    store_act<4, true>(acc, QB1, HG, 132, tx, ty);
    __syncthreads();

    float partial = 0.f;
    {
        const float* gh = HG + l * 132 + p * 32;
        const float* gw = QW2s + p * 32;
#pragma unroll 8
        for (int j = 0; j < 32; j++) partial += gh[j] * gw[j];
    }
    partial += __shfl_xor_sync(0xffffffffu, partial, 1);
    partial += __shfl_xor_sync(0xffffffffu, partial, 2);
    float gate = partial + QB2[0];

    if (p == 0 && n < N) {
        float invc = 1.0f / fmaxf(cnt[n], 1.0f);
        const float* fi = fsum + (size_t)n * 12;
        const float* ei = equ_in + (size_t)n * 9;
        float* eo = equ_out + (size_t)n * 9;
#pragma unroll
        for (int i = 0; i < 9; i++) {
            float tf = fi[i] * invc;
            tf = fminf(fmaxf(tf, -100.f), 100.f);
            eo[i] = gate * ei[i] + tf;
        }
    }

    gemm_t<4, 256>(CAT + ty * 4 * 260, 260, NW1, WS, tx, wk, wc, acc);
    __syncthreads();
    store_act<4, true>(acc, NB1, HG, 132, tx, ty);
    gemm_t<4, 128>(HG + ty * 4 * 132, 132, NW2, WS, tx, wk, wc, acc);
    {
        float bs[8];
#pragma unroll
        for (int cp = 0; cp < 4; cp++) {
            float2 bb = *(const float2*)(NB2 + tx * 2 + 32 * cp);
            bs[2 * cp] = bb.x; bs[2 * cp + 1] = bb.y;
        }
#pragma unroll
        for (int rr = 0; rr < 4; rr++) {
            int nn = n0 + ty * 4 + rr;
            if (nn < N) {
                float* op = h_out + (size_t)nn * 128 + tx * 2;
#pragma unroll
                for (int cp = 0; cp < 4; cp++) {
                    float x0, x1; unpack2(acc[rr][cp], x0, x1);
                    *(float2*)(op + 32 * cp) = make_float2(x0 + bs[2 * cp], x1 + bs[2 * cp + 1]);
                }
            }
        }
    }
}

__global__ void embed_kernel(const float* __restrict__ h, const float* __restrict__ W,
                             const float* __restrict__ b, float* __restrict__ out)
{
    __shared__ float hs[16];
    int n = blockIdx.x, c = threadIdx.x;
    if (c < 16) hs[c] = h[n * 16 + c];
    __syncthreads();
    float a = b[c];
#pragma unroll
    for (int k = 0; k < 16; k++) a += hs[k] * W[k * 128 + c];
    out[(size_t)n * 128 + c] = a;
}

__global__ void deg_kernel(const int* __restrict__ erow, float* __restrict__ cnt)
{
    int e = blockIdx.x * 256 + threadIdx.x;
    if (e < EE) atomicAdd(cnt + erow[e], 1.0f);
}

extern "C" void kernel_launch(void* const* d_in, const int* in_sizes, int n_in,
                              void* d_out, int out_size)
{
    (void)in_sizes; (void)n_in; (void)out_size;
    const float* equ   = (const float*)d_in[0];
    const float* h_in  = (const float*)d_in[1];
    const float* efea  = (const float*)d_in[2];
    const float* embW  = (const float*)d_in[3];
    const float* embB  = (const float*)d_in[4];
    const float* msgW1 = (const float*)d_in[5];
    const float* msgB1 = (const float*)d_in[6];
    const float* msgW2 = (const float*)d_in[7];
    const float* msgB2 = (const float*)d_in[8];
    const float* cW1   = (const float*)d_in[9];
    const float* cB1   = (const float*)d_in[10];
    const float* cW2   = (const float*)d_in[11];
    const float* cB2   = (const float*)d_in[12];
    const float* nW1   = (const float*)d_in[13];
    const float* nB1   = (const float*)d_in[14];
    const float* nW2   = (const float*)d_in[15];
    const float* nB2   = (const float*)d_in[16];
    const float* qW1   = (const float*)d_in[17];
    const float* qB1   = (const float*)d_in[18];
    const float* qW2   = (const float*)d_in[19];
    const float* qB2   = (const float*)d_in[20];
    const int*   eidx  = (const int*)d_in[21];
    const int* erow = eidx;
    const int* ecol = eidx + EE;
    float* out = (float*)d_out;

    cudaFuncSetAttribute(edge_kernel, cudaFuncAttributeMaxDynamicSharedMemorySize, E_SMEM_BYTES);
    cudaFuncSetAttribute(node_kernel, cudaFuncAttributeMaxDynamicSharedMemorySize, N_SMEM_BYTES);
    cudaFuncSetAttribute(prep_kernel, cudaFuncAttributeMaxDynamicSharedMemorySize, P_SMEM_BYTES);

    float *p_h0, *p_h1, *p_equ1, *p_fsum, *p_msum, *p_cnt, *p_Pr, *p_Pc;
    cudaGetSymbolAddress((void**)&p_h0, g_h0);
    cudaGetSymbolAddress((void**)&p_h1, g_h1);
    cudaGetSymbolAddress((void**)&p_equ1, g_equ1);
    cudaGetSymbolAddress((void**)&p_fsum, g_fsum);
    cudaGetSymbolAddress((void**)&p_msum, g_msum);
    cudaGetSymbolAddress((void**)&p_cnt, g_cnt);
    cudaGetSymbolAddress((void**)&p_Pr, g_Pr);
    cudaGetSymbolAddress((void**)&p_Pc, g_Pc);

    cudaMemsetAsync(p_cnt, 0, NN * sizeof(float));
    deg_kernel<<<(EE + 255) / 256, 256>>>(erow, p_cnt);
    embed_kernel<<<NN, 128>>>(h_in, embW, embB, p_h0);

    const int nblk = (NN + 63) / 64;

    for (int i = 0; i < 2; i++) {
        const float* h_cur   = (i == 0) ? p_h0 : p_h1;
        const float* equ_cur = (i == 0) ? equ : p_equ1;
        float* equ_nxt = (i == 0) ? p_equ1 : out;
        float* h_nxt   = (i == 0) ? p_h1 : (out + NN * 9);

        cudaMemsetAsync(p_fsum, 0, NN * 12 * sizeof(float));
        cudaMemsetAsync(p_msum, 0, (size_t)NN * HH * sizeof(float));

        prep_kernel<<<nblk, 256, P_SMEM_BYTES>>>(
            h_cur, msgW1 + (size_t)i * 267 * 128, msgB1 + i * 128, p_Pr, p_Pc, NN);

        edge_kernel<<<EE / 64, 256, E_SMEM_BYTES>>>(
            equ_cur, p_Pr, p_Pc, efea, erow, ecol,
            msgW1 + (size_t)i * 267 * 128,
            msgW2 + (size_t)i * 128 * 128, msgB2 + i * 128,
            cW1 + (size_t)i * 128 * 128, cB1 + i * 128,
            cW2 + (size_t)i * 128, cB2 + i,
            p_fsum, p_msum);

        node_kernel<<<nblk, 256, N_SMEM_BYTES>>>(
            h_cur, equ_cur, p_fsum, p_msum, p_cnt,
            nW1 + (size_t)i * 256 * 128, nB1 + i * 128,
            nW2 + (size_t)i * 128 * 128, nB2 + i * 128,
            qW1 + (size_t)i * 128 * 128, qB1 + i * 128,
            qW2 + (size_t)i * 128, qB2 + i,
            equ_nxt, h_nxt, NN);
    }
}

// round 6
// speedup vs baseline: 1.5526x; 1.0324x over previous
#include <cuda_runtime.h>
#include <math.h>

typedef unsigned long long ull;

#define NN 20000
#define EE 640000
#define HH 128

__device__ __forceinline__ ull pack2(float x, float y) {
    ull r; asm("mov.b64 %0, {%1, %2};" : "=l"(r) : "f"(x), "f"(y)); return r;
}
__device__ __forceinline__ void unpack2(ull v, float& x, float& y) {
    asm("mov.b64 {%0, %1}, %2;" : "=f"(x), "=f"(y) : "l"(v));
}
__device__ __forceinline__ void fma2(ull& d, ull a, ull b) {
    asm("fma.rn.f32x2 %0, %1, %2, %0;" : "+l"(d) : "l"(a), "l"(b));
}
__device__ __forceinline__ float silu_f(float x) { return x / (1.0f + expf(-x)); }

__device__ __forceinline__ void red4(float* p, float a, float b, float c, float d) {
    asm volatile("red.global.add.v4.f32 [%0], {%1, %2, %3, %4};"
                 :: "l"(p), "f"(a), "f"(b), "f"(c), "f"(d) : "memory");
}

// ---------------- scratch ----------------
__device__ float g_h0[NN * HH];
__device__ float g_h1[NN * HH];
__device__ float g_equ1[NN * 9];
__device__ float g_fsum[NN * 12];
__device__ float g_msum[NN * HH];
__device__ float g_cnt[NN];
__device__ float g_Pr[NN * HH];
__device__ float g_Pc[NN * HH];

// ---------------- tiled GEMM (256 thr, ROWSx8 micro-tile, f32x2) ----------------
// Thread (tx,ty) owns cols {tx*4+0..3} and {tx*4+64..67}:
//   acc[rr][0..1] = group0 pairs, acc[rr][2..3] = group1 pairs.
// B fetched as 2x LDS.128 per k (conflict-free, 2 wavefronts each);
// A fetched as LDS.64 pairs across k (broadcast).
// Weight chunk k+1 is prefetched into registers during compute of chunk k.
template<int ROWS, int KPAD>
__device__ __forceinline__ void gemm_t(const float* As, int lda,
                                       const float* __restrict__ Wg,
                                       float* WS, int tx, int wk, int wc,
                                       ull (&acc)[ROWS][4])
{
    const float* wp0 = Wg + (size_t)wk * 128 + wc;
    float4 v0 = *(const float4*)(wp0);
    float4 v1 = *(const float4*)(wp0 + 4);
    float4 v2 = *(const float4*)(wp0 + 8);
    float4 v3 = *(const float4*)(wp0 + 12);
#pragma unroll 1
    for (int kc = 0; kc < KPAD; kc += 32) {
        __syncthreads();     // previous WS readers done
        {
            float4* wsp = (float4*)(WS + wk * 128 + wc);
            wsp[0] = v0; wsp[1] = v1; wsp[2] = v2; wsp[3] = v3;
        }
        __syncthreads();     // chunk staged
        if (kc + 32 < KPAD) {
            const float* wn = Wg + (size_t)(kc + 32 + wk) * 128 + wc;
            v0 = *(const float4*)(wn);
            v1 = *(const float4*)(wn + 4);
            v2 = *(const float4*)(wn + 8);
            v3 = *(const float4*)(wn + 12);
        }
        const float* Arow = As + kc;
        const float* Bcol = WS + tx * 4;
#pragma unroll 2
        for (int kk = 0; kk < 32; kk += 2) {
            float4 b0a = *(const float4*)(Bcol + kk * 128);
            float4 b1a = *(const float4*)(Bcol + kk * 128 + 64);
            float4 b0b = *(const float4*)(Bcol + (kk + 1) * 128);
            float4 b1b = *(const float4*)(Bcol + (kk + 1) * 128 + 64);
            ull b00 = pack2(b0a.x, b0a.y), b01 = pack2(b0a.z, b0a.w);
            ull b10 = pack2(b1a.x, b1a.y), b11 = pack2(b1a.z, b1a.w);
            ull c00 = pack2(b0b.x, b0b.y), c01 = pack2(b0b.z, b0b.w);
            ull c10 = pack2(b1b.x, b1b.y), c11 = pack2(b1b.z, b1b.w);
#pragma unroll
            for (int rr = 0; rr < ROWS; rr++) {
                float2 a = *(const float2*)(Arow + rr * lda + kk);
                ull a0 = pack2(a.x, a.x);
                ull a1 = pack2(a.y, a.y);
                fma2(acc[rr][0], a0, b00);
                fma2(acc[rr][1], a0, b01);
                fma2(acc[rr][2], a0, b10);
                fma2(acc[rr][3], a0, b11);
                fma2(acc[rr][0], a1, c00);
                fma2(acc[rr][1], a1, c01);
                fma2(acc[rr][2], a1, c10);
                fma2(acc[rr][3], a1, c11);
            }
        }
    }
}

template<int ROWS, bool SILU>
__device__ __forceinline__ void store_act(ull (&acc)[ROWS][4],
                                          const float* __restrict__ bias,
                                          float* dst, int ldd, int tx, int ty)
{
    float4 bg0 = *(const float4*)(bias + tx * 4);
    float4 bg1 = *(const float4*)(bias + tx * 4 + 64);
#pragma unroll
    for (int rr = 0; rr < ROWS; rr++) {
        float* orow = dst + (ty * ROWS + rr) * ldd + tx * 4;
        float x0, x1, x2, x3;
        unpack2(acc[rr][0], x0, x1); unpack2(acc[rr][1], x2, x3);
        x0 += bg0.x; x1 += bg0.y; x2 += bg0.z; x3 += bg0.w;
        if (SILU) { x0 = silu_f(x0); x1 = silu_f(x1); x2 = silu_f(x2); x3 = silu_f(x3); }
        *(float4*)(orow) = make_float4(x0, x1, x2, x3);
        unpack2(acc[rr][2], x0, x1); unpack2(acc[rr][3], x2, x3);
        x0 += bg1.x; x1 += bg1.y; x2 += bg1.z; x3 += bg1.w;
        if (SILU) { x0 = silu_f(x0); x1 = silu_f(x1); x2 = silu_f(x2); x3 = silu_f(x3); }
        *(float4*)(orow + 64) = make_float4(x0, x1, x2, x3);
        acc[rr][0] = acc[rr][1] = acc[rr][2] = acc[rr][3] = 0ull;
    }
}

template<int ROWS>
__device__ __forceinline__ void store_glob(ull (&acc)[ROWS][4], const float* bias,
                                           float* out, int n0, int tx, int ty, int N)
{
    float4 bg0, bg1;
    if (bias) {
        bg0 = *(const float4*)(bias + tx * 4);
        bg1 = *(const float4*)(bias + tx * 4 + 64);
    } else {
        bg0 = bg1 = make_float4(0.f, 0.f, 0.f, 0.f);
    }
#pragma unroll
    for (int rr = 0; rr < ROWS; rr++) {
        int nn = n0 + ty * ROWS + rr;
        float x0, x1, x2, x3;
        unpack2(acc[rr][0], x0, x1); unpack2(acc[rr][1], x2, x3);
        if (nn < N)
            *(float4*)(out + (size_t)nn * 128 + tx * 4) =
                make_float4(x0 + bg0.x, x1 + bg0.y, x2 + bg0.z, x3 + bg0.w);
        unpack2(acc[rr][2], x0, x1); unpack2(acc[rr][3], x2, x3);
        if (nn < N)
            *(float4*)(out + (size_t)nn * 128 + tx * 4 + 64) =
                make_float4(x0 + bg1.x, x1 + bg1.y, x2 + bg1.z, x3 + bg1.w);
        acc[rr][0] = acc[rr][1] = acc[rr][2] = acc[rr][3] = 0ull;
    }
}

// ---------------- prep: Pr = h@W1[3:131]+b1, Pc = h@W1[131:259] ----------------
#define P_SMEM_BYTES (12544 * 4)
__global__ __launch_bounds__(256, 2)
void prep_kernel(const float* __restrict__ hN, const float* __restrict__ W1,
                 const float* __restrict__ B1,
                 float* __restrict__ Pr, float* __restrict__ Pc, int N)
{
    extern __shared__ float sm[];
    float* A = sm;            // [64][132]
    float* WS = sm + 8448;    // [32][128]
    const int tid = threadIdx.x;
    const int l = tid >> 2, p = tid & 3;
    const int n0 = blockIdx.x * 64;
    const int n = n0 + l;
    {
        float* ar = A + l * 132 + p * 32;
        if (n < N) {
            const float4* hp = (const float4*)(hN + (size_t)n * 128 + p * 32);
#pragma unroll
            for (int j = 0; j < 8; j++) *(float4*)(ar + j * 4) = hp[j];
        } else {
#pragma unroll
            for (int j = 0; j < 8; j++) *(float4*)(ar + j * 4) = make_float4(0.f, 0.f, 0.f, 0.f);
        }
    }
    const int tx = tid & 15, ty = tid >> 4;
    const int wk = tid >> 3, wc = (tid & 7) * 16;
    ull acc[4][4];
#pragma unroll
    for (int i = 0; i < 4; i++)
#pragma unroll
        for (int j = 0; j < 4; j++) acc[i][j] = 0ull;

    gemm_t<4, 128>(A + ty * 4 * 132, 132, W1 + 3 * 128, WS, tx, wk, wc, acc);
    store_glob<4>(acc, B1, Pr, n0, tx, ty, N);
    gemm_t<4, 128>(A + ty * 4 * 132, 132, W1 + 131 * 128, WS, tx, wk, wc, acc);
    store_glob<4>(acc, (const float*)0, Pc, n0, tx, ty, N);
}

// ---------------- edge kernel: 64 edges / block ----------------
// floats: HID[64][132]@0 ; MSG@8448 ; WS@16896 ; RIJ[64][12]@20992 ; SCAL[64][12]@21760 ; W1SE[11][128]@22528
#define E_SMEM_FLOATS 23936
#define E_SMEM_BYTES (E_SMEM_FLOATS * 4)

__global__ __launch_bounds__(256, 2)
void edge_kernel(const float* __restrict__ equ,
                 const float* __restrict__ Pr, const float* __restrict__ Pc,
                 const float* __restrict__ efea,
                 const int* __restrict__ erow, const int* __restrict__ ecol,
                 const float* __restrict__ W1,
                 const float* __restrict__ W2, const float* __restrict__ B2,
                 const float* __restrict__ CW1, const float* __restrict__ CB1,
                 const float* __restrict__ CW2, const float* __restrict__ CB2,
                 float* __restrict__ fsum, float* __restrict__ msum)
{
    extern __shared__ float sm[];
    float* HID  = sm;
    float* MSG  = sm + 8448;
    float* WS   = sm + 16896;
    float* RIJ  = sm + 20992;
    float* SCAL = sm + 21760;
    float* W1SE = sm + 22528;

    const int tid = threadIdx.x;
    const int el = tid >> 2, p = tid & 3;
    const int e = blockIdx.x * 64 + el;
    const int r = erow[e], c = ecol[e];

    for (int idx = tid; idx < 11 * 128; idx += 256) {
        int row = idx >> 7, col = idx & 127;
        int grow = (row < 3) ? row : row + 256;
        W1SE[idx] = W1[grow * 128 + col];
    }
    if (p == 0) {
        const float* er_ = equ + (size_t)r * 9;
        const float* ec_ = equ + (size_t)c * 9;
        float rij[9];
#pragma unroll
        for (int i = 0; i < 9; i++) { rij[i] = er_[i] - ec_[i]; RIJ[el * 12 + i] = rij[i]; }
#pragma unroll
        for (int k = 0; k < 3; k++)
            SCAL[el * 12 + k] = sqrtf(rij[k] * rij[k] + rij[3 + k] * rij[3 + k] + rij[6 + k] * rij[6 + k]);
    } else if (p == 1) {
        const float4* ef = (const float4*)(efea + (size_t)e * 8);
        float4 a = ef[0], b = ef[1];
        SCAL[el * 12 + 3] = a.x; SCAL[el * 12 + 4] = a.y; SCAL[el * 12 + 5] = a.z; SCAL[el * 12 + 6] = a.w;
        SCAL[el * 12 + 7] = b.x; SCAL[el * 12 + 8] = b.y; SCAL[el * 12 + 9] = b.z; SCAL[el * 12 + 10] = b.w;
    }
    __syncthreads();

    // hidden = silu(Pr[r] + Pc[c] + s . W1se)
    {
        float s[11];
#pragma unroll
        for (int j = 0; j < 11; j++) s[j] = SCAL[el * 12 + j];
        const float4* pr = (const float4*)(Pr + (size_t)r * 128 + p * 32);
        const float4* pc = (const float4*)(Pc + (size_t)c * 128 + p * 32);
        float* hrow = HID + el * 132 + p * 32;
#pragma unroll
        for (int cg = 0; cg < 8; cg++) {
            float4 a = pr[cg], b = pc[cg];
            float4 v = make_float4(a.x + b.x, a.y + b.y, a.z + b.z, a.w + b.w);
#pragma unroll
            for (int j = 0; j < 11; j++) {
                float4 w = *(const float4*)(W1SE + j * 128 + p * 32 + cg * 4);
                v.x += s[j] * w.x; v.y += s[j] * w.y; v.z += s[j] * w.z; v.w += s[j] * w.w;
            }
            *(float4*)(hrow + cg * 4) = make_float4(silu_f(v.x), silu_f(v.y), silu_f(v.z), silu_f(v.w));
        }
    }

    const int tx = tid & 15, ty = tid >> 4;
    const int wk = tid >> 3, wc = (tid & 7) * 16;
    ull acc[4][4];
#pragma unroll
    for (int i = 0; i < 4; i++)
#pragma unroll
        for (int j = 0; j < 4; j++) acc[i][j] = 0ull;

    // message = silu(hidden @ W2 + b2)
    gemm_t<4, 128>(HID + ty * 4 * 132, 132, W2, WS, tx, wk, wc, acc);
    store_act<4, true>(acc, B2, MSG, 132, tx, ty);
    // ch = silu(message @ CW1 + cb1) -> HID
    gemm_t<4, 128>(MSG + ty * 4 * 132, 132, CW1, WS, tx, wk, wc, acc);
    __syncthreads();
    store_act<4, true>(acc, CB1, HID, 132, tx, ty);
    __syncthreads();

    // cms = ch . CW2 + cb2
    float partial = 0.f;
    {
        const float* chrow = HID + el * 132 + p * 32;
        const float* wv = CW2 + p * 32;
#pragma unroll 8
        for (int j = 0; j < 32; j++) partial += chrow[j] * wv[j];
    }
    partial += __shfl_xor_sync(0xffffffffu, partial, 1);
    partial += __shfl_xor_sync(0xffffffffu, partial, 2);
    float cms = partial + CB2[0];

    // scatter (vectorized red)
    if (p == 0) {
        const float* rj = RIJ + el * 12;
        float* fs = fsum + (size_t)r * 12;
        red4(fs, rj[0] * cms, rj[1] * cms, rj[2] * cms, rj[3] * cms);
        red4(fs + 4, rj[4] * cms, rj[5] * cms, rj[6] * cms, rj[7] * cms);
        atomicAdd(fs + 8, rj[8] * cms);
    }
    {
        const float* mg = MSG + el * 132 + p * 32;
        float* ms = msum + (size_t)r * 128 + p * 32;
#pragma unroll
        for (int i = 0; i < 8; i++)
            red4(ms + i * 4, mg[i * 4], mg[i * 4 + 1], mg[i * 4 + 2], mg[i * 4 + 3]);
    }
}

// ---------------- node kernel: 64 nodes / block ----------------
#define N_SMEM_FLOATS 29312
#define N_SMEM_BYTES (N_SMEM_FLOATS * 4)

__global__ __launch_bounds__(256, 1)
void node_kernel(const float* __restrict__ hN, const float* __restrict__ equ_in,
                 const float* __restrict__ fsum, const float* __restrict__ msum,
                 const float* __restrict__ cnt,
                 const float* __restrict__ NW1, const float* __restrict__ NB1,
                 const float* __restrict__ NW2, const float* __restrict__ NB2,
                 const float* __restrict__ QW1, const float* __restrict__ QB1,
                 const float* __restrict__ QW2, const float* __restrict__ QB2,
                 float* __restrict__ equ_out, float* __restrict__ h_out, int N)
{
    extern __shared__ float sm[];
    float* CAT = sm;            // [64][260]
    float* WS  = sm + 16640;
    float* HG  = sm + 20736;    // [64][132]
    float* QW2s = sm + 29184;

    const int tid = threadIdx.x;
    const int l = tid >> 2, p = tid & 3;
    const int n0 = blockIdx.x * 64;
    const int n = n0 + l;
    {
        float* cr = CAT + l * 260;
        if (n < N) {
            const float4* hp = (const float4*)(hN + (size_t)n * 128);
            const float4* mp = (const float4*)(msum + (size_t)n * 128);
#pragma unroll
            for (int j = 0; j < 8; j++) {
                *(float4*)(cr + (p * 8 + j) * 4) = hp[p * 8 + j];
                *(float4*)(cr + 128 + (p * 8 + j) * 4) = mp[p * 8 + j];
            }
        } else {
#pragma unroll
            for (int j = 0; j < 8; j++) {
                *(float4*)(cr + (p * 8 + j) * 4) = make_float4(0.f, 0.f, 0.f, 0.f);
                *(float4*)(cr + 128 + (p * 8 + j) * 4) = make_float4(0.f, 0.f, 0.f, 0.f);
            }
        }
    }
    if (tid < 128) QW2s[tid] = QW2[tid];

    const int tx = tid & 15, ty = tid >> 4;
    const int wk = tid >> 3, wc = (tid & 7) * 16;
    ull acc[4][4];
#pragma unroll
    for (int i = 0; i < 4; i++)
#pragma unroll
        for (int j = 0; j < 4; j++) acc[i][j] = 0ull;

    gemm_t<4, 128>(CAT + ty * 4 * 260, 260, QW1, WS, tx, wk, wc, acc);
    __syncthreads();
    store_act<4, true>(acc, QB1, HG, 132, tx, ty);
    __syncthreads();

    float partial = 0.f;
    {
        const float* gh = HG + l * 132 + p * 32;
        const float* gw = QW2s + p * 32;
#pragma unroll 8
        for (int j = 0; j < 32; j++) partial += gh[j] * gw[j];
    }
    partial += __shfl_xor_sync(0xffffffffu, partial, 1);
    partial += __shfl_xor_sync(0xffffffffu, partial, 2);
    float gate = partial + QB2[0];

    if (p == 0 && n < N) {
        float invc = 1.0f / fmaxf(cnt[n], 1.0f);
        const float* fi = fsum + (size_t)n * 12;
        const float* ei = equ_in + (size_t)n * 9;
        float* eo = equ_out + (size_t)n * 9;
#pragma unroll
        for (int i = 0; i < 9; i++) {
            float tf = fi[i] * invc;
            tf = fminf(fmaxf(tf, -100.f), 100.f);
            eo[i] = gate * ei[i] + tf;
        }
    }

    gemm_t<4, 256>(CAT + ty * 4 * 260, 260, NW1, WS, tx, wk, wc, acc);
    __syncthreads();
    store_act<4, true>(acc, NB1, HG, 132, tx, ty);
    gemm_t<4, 128>(HG + ty * 4 * 132, 132, NW2, WS, tx, wk, wc, acc);
    {
        float4 bg0 = *(const float4*)(NB2 + tx * 4);
        float4 bg1 = *(const float4*)(NB2 + tx * 4 + 64);
#pragma unroll
        for (int rr = 0; rr < 4; rr++) {
            int nn = n0 + ty * 4 + rr;
            if (nn < N) {
                float* op = h_out + (size_t)nn * 128 + tx * 4;
                float x0, x1, x2, x3;
                unpack2(acc[rr][0], x0, x1); unpack2(acc[rr][1], x2, x3);
                *(float4*)(op) = make_float4(x0 + bg0.x, x1 + bg0.y, x2 + bg0.z, x3 + bg0.w);
                unpack2(acc[rr][2], x0, x1); unpack2(acc[rr][3], x2, x3);
                *(float4*)(op + 64) = make_float4(x0 + bg1.x, x1 + bg1.y, x2 + bg1.z, x3 + bg1.w);
            }
        }
    }
}

__global__ void embed_kernel(const float* __restrict__ h, const float* __restrict__ W,
                             const float* __restrict__ b, float* __restrict__ out)
{
    __shared__ float hs[16];
    int n = blockIdx.x, c = threadIdx.x;
    if (c < 16) hs[c] = h[n * 16 + c];
    __syncthreads();
    float a = b[c];
#pragma unroll
    for (int k = 0; k < 16; k++) a += hs[k] * W[k * 128 + c];
    out[(size_t)n * 128 + c] = a;
}

__global__ void deg_kernel(const int* __restrict__ erow, float* __restrict__ cnt)
{
    int e = blockIdx.x * 256 + threadIdx.x;
    if (e < EE) atomicAdd(cnt + erow[e], 1.0f);
}

extern "C" void kernel_launch(void* const* d_in, const int* in_sizes, int n_in,
                              void* d_out, int out_size)
{
    (void)in_sizes; (void)n_in; (void)out_size;
    const float* equ   = (const float*)d_in[0];
    const float* h_in  = (const float*)d_in[1];
    const float* efea  = (const float*)d_in[2];
    const float* embW  = (const float*)d_in[3];
    const float* embB  = (const float*)d_in[4];
    const float* msgW1 = (const float*)d_in[5];
    const float* msgB1 = (const float*)d_in[6];
    const float* msgW2 = (const float*)d_in[7];
    const float* msgB2 = (const float*)d_in[8];
    const float* cW1   = (const float*)d_in[9];
    const float* cB1   = (const float*)d_in[10];
    const float* cW2   = (const float*)d_in[11];
    const float* cB2   = (const float*)d_in[12];
    const float* nW1   = (const float*)d_in[13];
    const float* nB1   = (const float*)d_in[14];
    const float* nW2   = (const float*)d_in[15];
    const float* nB2   = (const float*)d_in[16];
    const float* qW1   = (const float*)d_in[17];
    const float* qB1   = (const float*)d_in[18];
    const float* qW2   = (const float*)d_in[19];
    const float* qB2   = (const float*)d_in[20];
    const int*   eidx  = (const int*)d_in[21];
    const int* erow = eidx;
    const int* ecol = eidx + EE;
    float* out = (float*)d_out;

    cudaFuncSetAttribute(edge_kernel, cudaFuncAttributeMaxDynamicSharedMemorySize, E_SMEM_BYTES);
    cudaFuncSetAttribute(node_kernel, cudaFuncAttributeMaxDynamicSharedMemorySize, N_SMEM_BYTES);
    cudaFuncSetAttribute(prep_kernel, cudaFuncAttributeMaxDynamicSharedMemorySize, P_SMEM_BYTES);

    float *p_h0, *p_h1, *p_equ1, *p_fsum, *p_msum, *p_cnt, *p_Pr, *p_Pc;
    cudaGetSymbolAddress((void**)&p_h0, g_h0);
    cudaGetSymbolAddress((void**)&p_h1, g_h1);
    cudaGetSymbolAddress((void**)&p_equ1, g_equ1);
    cudaGetSymbolAddress((void**)&p_fsum, g_fsum);
    cudaGetSymbolAddress((void**)&p_msum, g_msum);
    cudaGetSymbolAddress((void**)&p_cnt, g_cnt);
    cudaGetSymbolAddress((void**)&p_Pr, g_Pr);
    cudaGetSymbolAddress((void**)&p_Pc, g_Pc);

    cudaMemsetAsync(p_cnt, 0, NN * sizeof(float));
    deg_kernel<<<(EE + 255) / 256, 256>>>(erow, p_cnt);
    embed_kernel<<<NN, 128>>>(h_in, embW, embB, p_h0);

    const int nblk = (NN + 63) / 64;

    for (int i = 0; i < 2; i++) {
        const float* h_cur   = (i == 0) ? p_h0 : p_h1;
        const float* equ_cur = (i == 0) ? equ : p_equ1;
        float* equ_nxt = (i == 0) ? p_equ1 : out;
        float* h_nxt   = (i == 0) ? p_h1 : (out + NN * 9);

        cudaMemsetAsync(p_fsum, 0, NN * 12 * sizeof(float));
        cudaMemsetAsync(p_msum, 0, (size_t)NN * HH * sizeof(float));

        prep_kernel<<<nblk, 256, P_SMEM_BYTES>>>(
            h_cur, msgW1 + (size_t)i * 267 * 128, msgB1 + i * 128, p_Pr, p_Pc, NN);

        edge_kernel<<<EE / 64, 256, E_SMEM_BYTES>>>(
            equ_cur, p_Pr, p_Pc, efea, erow, ecol,
            msgW1 + (size_t)i * 267 * 128,
            msgW2 + (size_t)i * 128 * 128, msgB2 + i * 128,
            cW1 + (size_t)i * 128 * 128, cB1 + i * 128,
            cW2 + (size_t)i * 128, cB2 + i,
            p_fsum, p_msum);

        node_kernel<<<nblk, 256, N_SMEM_BYTES>>>(
            h_cur, equ_cur, p_fsum, p_msum, p_cnt,
            nW1 + (size_t)i * 256 * 128, nB1 + i * 128,
            nW2 + (size_t)i * 128 * 128, nB2 + i * 128,
            qW1 + (size_t)i * 128 * 128, qB1 + i * 128,
            qW2 + (size_t)i * 128, qB2 + i,
            equ_nxt, h_nxt, NN);
    }
}

// round 7
// speedup vs baseline: 1.5558x; 1.0021x over previous
#include <cuda_runtime.h>
#include <math.h>

typedef unsigned long long ull;

#define NN 20000
#define EE 640000
#define HH 128

__device__ __forceinline__ ull pack2(float x, float y) {
    ull r; asm("mov.b64 %0, {%1, %2};" : "=l"(r) : "f"(x), "f"(y)); return r;
}
__device__ __forceinline__ void unpack2(ull v, float& x, float& y) {
    asm("mov.b64 {%0, %1}, %2;" : "=f"(x), "=f"(y) : "l"(v));
}
__device__ __forceinline__ void fma2(ull& d, ull a, ull b) {
    asm("fma.rn.f32x2 %0, %1, %2, %0;" : "+l"(d) : "l"(a), "l"(b));
}
__device__ __forceinline__ float silu_f(float x) { return x / (1.0f + expf(-x)); }

__device__ __forceinline__ void red4(float* p, float a, float b, float c, float d) {
    asm volatile("red.global.add.v4.f32 [%0], {%1, %2, %3, %4};"
                 :: "l"(p), "f"(a), "f"(b), "f"(c), "f"(d) : "memory");
}

// ---------------- scratch ----------------
__device__ float g_h0[NN * HH];
__device__ float g_h1[NN * HH];
__device__ float g_equ1[NN * 9];
__device__ float g_fsum[NN * 12];
__device__ float g_msum[NN * HH];
__device__ float g_cnt[NN];
__device__ float g_Pr[NN * HH];
__device__ float g_Pc[NN * HH];

// ---------------- tiled GEMM (256 thr, ROWSx8 micro-tile, f32x2) ----------------
// Thread (tx,ty) owns cols {tx*4+0..3} and {tx*4+64..67}:
//   acc[rr][0..1] = group0 pairs, acc[rr][2..3] = group1 pairs.
// B fetched as 2x LDS.128 per k (conflict-free, 2 wavefronts each);
// A fetched as LDS.64 pairs across k (broadcast).
// Weight chunk k+1 is prefetched into registers during compute of chunk k.
template<int ROWS, int KPAD>
__device__ __forceinline__ void gemm_t(const float* As, int lda,
                                       const float* __restrict__ Wg,
                                       float* WS, int tx, int wk, int wc,
                                       ull (&acc)[ROWS][4])
{
    const float* wp0 = Wg + (size_t)wk * 128 + wc;
    float4 v0 = *(const float4*)(wp0);
    float4 v1 = *(const float4*)(wp0 + 4);
    float4 v2 = *(const float4*)(wp0 + 8);
    float4 v3 = *(const float4*)(wp0 + 12);
#pragma unroll 1
    for (int kc = 0; kc < KPAD; kc += 32) {
        __syncthreads();     // previous WS readers done
        {
            float4* wsp = (float4*)(WS + wk * 128 + wc);
            wsp[0] = v0; wsp[1] = v1; wsp[2] = v2; wsp[3] = v3;
        }
        __syncthreads();     // chunk staged
        if (kc + 32 < KPAD) {
            const float* wn = Wg + (size_t)(kc + 32 + wk) * 128 + wc;
            v0 = *(const float4*)(wn);
            v1 = *(const float4*)(wn + 4);
            v2 = *(const float4*)(wn + 8);
            v3 = *(const float4*)(wn + 12);
        }
        const float* Arow = As + kc;
        const float* Bcol = WS + tx * 4;
#pragma unroll 2
        for (int kk = 0; kk < 32; kk += 2) {
            float4 b0a = *(const float4*)(Bcol + kk * 128);
            float4 b1a = *(const float4*)(Bcol + kk * 128 + 64);
            float4 b0b = *(const float4*)(Bcol + (kk + 1) * 128);
            float4 b1b = *(const float4*)(Bcol + (kk + 1) * 128 + 64);
            ull b00 = pack2(b0a.x, b0a.y), b01 = pack2(b0a.z, b0a.w);
            ull b10 = pack2(b1a.x, b1a.y), b11 = pack2(b1a.z, b1a.w);
            ull c00 = pack2(b0b.x, b0b.y), c01 = pack2(b0b.z, b0b.w);
            ull c10 = pack2(b1b.x, b1b.y), c11 = pack2(b1b.z, b1b.w);
#pragma unroll
            for (int rr = 0; rr < ROWS; rr++) {
                float2 a = *(const float2*)(Arow + rr * lda + kk);
                ull a0 = pack2(a.x, a.x);
                ull a1 = pack2(a.y, a.y);
                fma2(acc[rr][0], a0, b00);
                fma2(acc[rr][1], a0, b01);
                fma2(acc[rr][2], a0, b10);
                fma2(acc[rr][3], a0, b11);
                fma2(acc[rr][0], a1, c00);
                fma2(acc[rr][1], a1, c01);
                fma2(acc[rr][2], a1, c10);
                fma2(acc[rr][3], a1, c11);
            }
        }
    }
}

template<int ROWS, bool SILU>
__device__ __forceinline__ void store_act(ull (&acc)[ROWS][4],
                                          const float* __restrict__ bias,
                                          float* dst, int ldd, int tx, int ty)
{
    float4 bg0 = *(const float4*)(bias + tx * 4);
    float4 bg1 = *(const float4*)(bias + tx * 4 + 64);
#pragma unroll
    for (int rr = 0; rr < ROWS; rr++) {
        float* orow = dst + (ty * ROWS + rr) * ldd + tx * 4;
        float x0, x1, x2, x3;
        unpack2(acc[rr][0], x0, x1); unpack2(acc[rr][1], x2, x3);
        x0 += bg0.x; x1 += bg0.y; x2 += bg0.z; x3 += bg0.w;
        if (SILU) { x0 = silu_f(x0); x1 = silu_f(x1); x2 = silu_f(x2); x3 = silu_f(x3); }
        *(float4*)(orow) = make_float4(x0, x1, x2, x3);
        unpack2(acc[rr][2], x0, x1); unpack2(acc[rr][3], x2, x3);
        x0 += bg1.x; x1 += bg1.y; x2 += bg1.z; x3 += bg1.w;
        if (SILU) { x0 = silu_f(x0); x1 = silu_f(x1); x2 = silu_f(x2); x3 = silu_f(x3); }
        *(float4*)(orow + 64) = make_float4(x0, x1, x2, x3);
        acc[rr][0] = acc[rr][1] = acc[rr][2] = acc[rr][3] = 0ull;
    }
}

template<int ROWS>
__device__ __forceinline__ void store_glob(ull (&acc)[ROWS][4], const float* bias,
                                           float* out, int n0, int tx, int ty, int N)
{
    float4 bg0, bg1;
    if (bias) {
        bg0 = *(const float4*)(bias + tx * 4);
        bg1 = *(const float4*)(bias + tx * 4 + 64);
    } else {
        bg0 = bg1 = make_float4(0.f, 0.f, 0.f, 0.f);
    }
#pragma unroll
    for (int rr = 0; rr < ROWS; rr++) {
        int nn = n0 + ty * ROWS + rr;
        float x0, x1, x2, x3;
        unpack2(acc[rr][0], x0, x1); unpack2(acc[rr][1], x2, x3);
        if (nn < N)
            *(float4*)(out + (size_t)nn * 128 + tx * 4) =
                make_float4(x0 + bg0.x, x1 + bg0.y, x2 + bg0.z, x3 + bg0.w);
        unpack2(acc[rr][2], x0, x1); unpack2(acc[rr][3], x2, x3);
        if (nn < N)
            *(float4*)(out + (size_t)nn * 128 + tx * 4 + 64) =
                make_float4(x0 + bg1.x, x1 + bg1.y, x2 + bg1.z, x3 + bg1.w);
        acc[rr][0] = acc[rr][1] = acc[rr][2] = acc[rr][3] = 0ull;
    }
}

// ---------------- prep: Pr = h@W1[3:131]+b1, Pc = h@W1[131:259] ----------------
#define P_SMEM_BYTES (12544 * 4)
__global__ __launch_bounds__(256, 2)
void prep_kernel(const float* __restrict__ hN, const float* __restrict__ W1,
                 const float* __restrict__ B1,
                 float* __restrict__ Pr, float* __restrict__ Pc, int N)
{
    extern __shared__ float sm[];
    float* A = sm;            // [64][132]
    float* WS = sm + 8448;    // [32][128]
    const int tid = threadIdx.x;
    const int l = tid >> 2, p = tid & 3;
    const int n0 = blockIdx.x * 64;
    const int n = n0 + l;
    {
        float* ar = A + l * 132 + p * 32;
        if (n < N) {
            const float4* hp = (const float4*)(hN + (size_t)n * 128 + p * 32);
#pragma unroll
            for (int j = 0; j < 8; j++) *(float4*)(ar + j * 4) = hp[j];
        } else {
#pragma unroll
            for (int j = 0; j < 8; j++) *(float4*)(ar + j * 4) = make_float4(0.f, 0.f, 0.f, 0.f);
        }
    }
    const int tx = tid & 15, ty = tid >> 4;
    const int wk = tid >> 3, wc = (tid & 7) * 16;
    ull acc[4][4];
#pragma unroll
    for (int i = 0; i < 4; i++)
#pragma unroll
        for (int j = 0; j < 4; j++) acc[i][j] = 0ull;

    gemm_t<4, 128>(A + ty * 4 * 132, 132, W1 + 3 * 128, WS, tx, wk, wc, acc);
    store_glob<4>(acc, B1, Pr, n0, tx, ty, N);
    gemm_t<4, 128>(A + ty * 4 * 132, 132, W1 + 131 * 128, WS, tx, wk, wc, acc);
    store_glob<4>(acc, (const float*)0, Pc, n0, tx, ty, N);
}

// ---------------- edge kernel: 64 edges / block ----------------
// floats: HID[64][132]@0 ; MSG@8448 ; WS@16896 ; RIJ[64][12]@20992 ; SCAL[64][12]@21760 ; W1SE[11][128]@22528
#define E_SMEM_FLOATS 23936
#define E_SMEM_BYTES (E_SMEM_FLOATS * 4)

__global__ __launch_bounds__(256, 2)
void edge_kernel(const float* __restrict__ equ,
                 const float* __restrict__ Pr, const float* __restrict__ Pc,
                 const float* __restrict__ efea,
                 const int* __restrict__ erow, const int* __restrict__ ecol,
                 const float* __restrict__ W1,
                 const float* __restrict__ W2, const float* __restrict__ B2,
                 const float* __restrict__ CW1, const float* __restrict__ CB1,
                 const float* __restrict__ CW2, const float* __restrict__ CB2,
                 float* __restrict__ fsum, float* __restrict__ msum)
{
    extern __shared__ float sm[];
    float* HID  = sm;
    float* MSG  = sm + 8448;
    float* WS   = sm + 16896;
    float* RIJ  = sm + 20992;
    float* SCAL = sm + 21760;
    float* W1SE = sm + 22528;

    const int tid = threadIdx.x;
    const int el = tid >> 2, p = tid & 3;
    const int e = blockIdx.x * 64 + el;
    const int r = erow[e], c = ecol[e];

    for (int idx = tid; idx < 11 * 128; idx += 256) {
        int row = idx >> 7, col = idx & 127;
        int grow = (row < 3) ? row : row + 256;
        W1SE[idx] = W1[grow * 128 + col];
    }
    if (p == 0) {
        const float* er_ = equ + (size_t)r * 9;
        const float* ec_ = equ + (size_t)c * 9;
        float rij[9];
#pragma unroll
        for (int i = 0; i < 9; i++) { rij[i] = er_[i] - ec_[i]; RIJ[el * 12 + i] = rij[i]; }
#pragma unroll
        for (int k = 0; k < 3; k++)
            SCAL[el * 12 + k] = sqrtf(rij[k] * rij[k] + rij[3 + k] * rij[3 + k] + rij[6 + k] * rij[6 + k]);
    } else if (p == 1) {
        const float4* ef = (const float4*)(efea + (size_t)e * 8);
        float4 a = ef[0], b = ef[1];
        SCAL[el * 12 + 3] = a.x; SCAL[el * 12 + 4] = a.y; SCAL[el * 12 + 5] = a.z; SCAL[el * 12 + 6] = a.w;
        SCAL[el * 12 + 7] = b.x; SCAL[el * 12 + 8] = b.y; SCAL[el * 12 + 9] = b.z; SCAL[el * 12 + 10] = b.w;
    }
    __syncthreads();

    // hidden = silu(Pr[r] + Pc[c] + s . W1se)
    {
        float s[11];
#pragma unroll
        for (int j = 0; j < 11; j++) s[j] = SCAL[el * 12 + j];
        const float4* pr = (const float4*)(Pr + (size_t)r * 128 + p * 32);
        const float4* pc = (const float4*)(Pc + (size_t)c * 128 + p * 32);
        float* hrow = HID + el * 132 + p * 32;
#pragma unroll
        for (int cg = 0; cg < 8; cg++) {
            float4 a = pr[cg], b = pc[cg];
            float4 v = make_float4(a.x + b.x, a.y + b.y, a.z + b.z, a.w + b.w);
#pragma unroll
            for (int j = 0; j < 11; j++) {
                float4 w = *(const float4*)(W1SE + j * 128 + p * 32 + cg * 4);
                v.x += s[j] * w.x; v.y += s[j] * w.y; v.z += s[j] * w.z; v.w += s[j] * w.w;
            }
            *(float4*)(hrow + cg * 4) = make_float4(silu_f(v.x), silu_f(v.y), silu_f(v.z), silu_f(v.w));
        }
    }

    const int tx = tid & 15, ty = tid >> 4;
    const int wk = tid >> 3, wc = (tid & 7) * 16;
    ull acc[4][4];
#pragma unroll
    for (int i = 0; i < 4; i++)
#pragma unroll
        for (int j = 0; j < 4; j++) acc[i][j] = 0ull;

    // message = silu(hidden @ W2 + b2)
    gemm_t<4, 128>(HID + ty * 4 * 132, 132, W2, WS, tx, wk, wc, acc);
    store_act<4, true>(acc, B2, MSG, 132, tx, ty);
    // ch = silu(message @ CW1 + cb1) -> HID
    gemm_t<4, 128>(MSG + ty * 4 * 132, 132, CW1, WS, tx, wk, wc, acc);
    __syncthreads();
    store_act<4, true>(acc, CB1, HID, 132, tx, ty);
    __syncthreads();

    // cms = ch . CW2 + cb2
    float partial = 0.f;
    {
        const float* chrow = HID + el * 132 + p * 32;
        const float* wv = CW2 + p * 32;
#pragma unroll 8
        for (int j = 0; j < 32; j++) partial += chrow[j] * wv[j];
    }
    partial += __shfl_xor_sync(0xffffffffu, partial, 1);
    partial += __shfl_xor_sync(0xffffffffu, partial, 2);
    float cms = partial + CB2[0];

    // scatter (vectorized red)
    if (p == 0) {
        const float* rj = RIJ + el * 12;
        float* fs = fsum + (size_t)r * 12;
        red4(fs, rj[0] * cms, rj[1] * cms, rj[2] * cms, rj[3] * cms);
        red4(fs + 4, rj[4] * cms, rj[5] * cms, rj[6] * cms, rj[7] * cms);
        atomicAdd(fs + 8, rj[8] * cms);
    }
    {
        const float* mg = MSG + el * 132 + p * 32;
        float* ms = msum + (size_t)r * 128 + p * 32;
#pragma unroll
        for (int i = 0; i < 8; i++)
            red4(ms + i * 4, mg[i * 4], mg[i * 4 + 1], mg[i * 4 + 2], mg[i * 4 + 3]);
    }
}

// ---------------- node kernel: 64 nodes / block ----------------
#define N_SMEM_FLOATS 29312
#define N_SMEM_BYTES (N_SMEM_FLOATS * 4)

__global__ __launch_bounds__(256, 1)
void node_kernel(const float* __restrict__ hN, const float* __restrict__ equ_in,
                 const float* __restrict__ fsum, const float* __restrict__ msum,
                 const float* __restrict__ cnt,
                 const float* __restrict__ NW1, const float* __restrict__ NB1,
                 const float* __restrict__ NW2, const float* __restrict__ NB2,
                 const float* __restrict__ QW1, const float* __restrict__ QB1,
                 const float* __restrict__ QW2, const float* __restrict__ QB2,
                 float* __restrict__ equ_out, float* __restrict__ h_out, int N)
{
    extern __shared__ float sm[];
    float* CAT = sm;            // [64][260]
    float* WS  = sm + 16640;
    float* HG  = sm + 20736;    // [64][132]
    float* QW2s = sm + 29184;

    const int tid = threadIdx.x;
    const int l = tid >> 2, p = tid & 3;
    const int n0 = blockIdx.x * 64;
    const int n = n0 + l;
    {
        float* cr = CAT + l * 260;
        if (n < N) {
            const float4* hp = (const float4*)(hN + (size_t)n * 128);
            const float4* mp = (const float4*)(msum + (size_t)n * 128);
#pragma unroll
            for (int j = 0; j < 8; j++) {
                *(float4*)(cr + (p * 8 + j) * 4) = hp[p * 8 + j];
                *(float4*)(cr + 128 + (p * 8 + j) * 4) = mp[p * 8 + j];
            }
        } else {
#pragma unroll
            for (int j = 0; j < 8; j++) {
                *(float4*)(cr + (p * 8 + j) * 4) = make_float4(0.f, 0.f, 0.f, 0.f);
                *(float4*)(cr + 128 + (p * 8 + j) * 4) = make_float4(0.f, 0.f, 0.f, 0.f);
            }
        }
    }
    if (tid < 128) QW2s[tid] = QW2[tid];

    const int tx = tid & 15, ty = tid >> 4;
    const int wk = tid >> 3, wc = (tid & 7) * 16;
    ull acc[4][4];
#pragma unroll
    for (int i = 0; i < 4; i++)
#pragma unroll
        for (int j = 0; j < 4; j++) acc[i][j] = 0ull;

    gemm_t<4, 128>(CAT + ty * 4 * 260, 260, QW1, WS, tx, wk, wc, acc);
    __syncthreads();
    store_act<4, true>(acc, QB1, HG, 132, tx, ty);
    __syncthreads();

    float partial = 0.f;
    {
        const float* gh = HG + l * 132 + p * 32;
        const float* gw = QW2s + p * 32;
#pragma unroll 8
        for (int j = 0; j < 32; j++) partial += gh[j] * gw[j];
    }
    partial += __shfl_xor_sync(0xffffffffu, partial, 1);
    partial += __shfl_xor_sync(0xffffffffu, partial, 2);
    float gate = partial + QB2[0];

    if (p == 0 && n < N) {
        float invc = 1.0f / fmaxf(cnt[n], 1.0f);
        const float* fi = fsum + (size_t)n * 12;
        const float* ei = equ_in + (size_t)n * 9;
        float* eo = equ_out + (size_t)n * 9;
#pragma unroll
        for (int i = 0; i < 9; i++) {
            float tf = fi[i] * invc;
            tf = fminf(fmaxf(tf, -100.f), 100.f);
            eo[i] = gate * ei[i] + tf;
        }
    }

    gemm_t<4, 256>(CAT + ty * 4 * 260, 260, NW1, WS, tx, wk, wc, acc);
    __syncthreads();
    store_act<4, true>(acc, NB1, HG, 132, tx, ty);
    gemm_t<4, 128>(HG + ty * 4 * 132, 132, NW2, WS, tx, wk, wc, acc);
    {
        float4 bg0 = *(const float4*)(NB2 + tx * 4);
        float4 bg1 = *(const float4*)(NB2 + tx * 4 + 64);
#pragma unroll
        for (int rr = 0; rr < 4; rr++) {
            int nn = n0 + ty * 4 + rr;
            if (nn < N) {
                float* op = h_out + (size_t)nn * 128 + tx * 4;
                float x0, x1, x2, x3;
                unpack2(acc[rr][0], x0, x1); unpack2(acc[rr][1], x2, x3);
                *(float4*)(op) = make_float4(x0 + bg0.x, x1 + bg0.y, x2 + bg0.z, x3 + bg0.w);
                unpack2(acc[rr][2], x0, x1); unpack2(acc[rr][3], x2, x3);
                *(float4*)(op + 64) = make_float4(x0 + bg1.x, x1 + bg1.y, x2 + bg1.z, x3 + bg1.w);
            }
        }
    }
}

__global__ void embed_kernel(const float* __restrict__ h, const float* __restrict__ W,
                             const float* __restrict__ b, float* __restrict__ out)
{
    __shared__ float hs[16];
    int n = blockIdx.x, c = threadIdx.x;
    if (c < 16) hs[c] = h[n * 16 + c];
    __syncthreads();
    float a = b[c];
#pragma unroll
    for (int k = 0; k < 16; k++) a += hs[k] * W[k * 128 + c];
    out[(size_t)n * 128 + c] = a;
}

__global__ void deg_kernel(const int* __restrict__ erow, float* __restrict__ cnt)
{
    int e = blockIdx.x * 256 + threadIdx.x;
    if (e < EE) atomicAdd(cnt + erow[e], 1.0f);
}

extern "C" void kernel_launch(void* const* d_in, const int* in_sizes, int n_in,
                              void* d_out, int out_size)
{
    (void)in_sizes; (void)n_in; (void)out_size;
    const float* equ   = (const float*)d_in[0];
    const float* h_in  = (const float*)d_in[1];
    const float* efea  = (const float*)d_in[2];
    const float* embW  = (const float*)d_in[3];
    const float* embB  = (const float*)d_in[4];
    const float* msgW1 = (const float*)d_in[5];
    const float* msgB1 = (const float*)d_in[6];
    const float* msgW2 = (const float*)d_in[7];
    const float* msgB2 = (const float*)d_in[8];
    const float* cW1   = (const float*)d_in[9];
    const float* cB1   = (const float*)d_in[10];
    const float* cW2   = (const float*)d_in[11];
    const float* cB2   = (const float*)d_in[12];
    const float* nW1   = (const float*)d_in[13];
    const float* nB1   = (const float*)d_in[14];
    const float* nW2   = (const float*)d_in[15];
    const float* nB2   = (const float*)d_in[16];
    const float* qW1   = (const float*)d_in[17];
    const float* qB1   = (const float*)d_in[18];
    const float* qW2   = (const float*)d_in[19];
    const float* qB2   = (const float*)d_in[20];
    const int*   eidx  = (const int*)d_in[21];
    const int* erow = eidx;
    const int* ecol = eidx + EE;
    float* out = (float*)d_out;

    cudaFuncSetAttribute(edge_kernel, cudaFuncAttributeMaxDynamicSharedMemorySize, E_SMEM_BYTES);
    cudaFuncSetAttribute(node_kernel, cudaFuncAttributeMaxDynamicSharedMemorySize, N_SMEM_BYTES);
    cudaFuncSetAttribute(prep_kernel, cudaFuncAttributeMaxDynamicSharedMemorySize, P_SMEM_BYTES);

    float *p_h0, *p_h1, *p_equ1, *p_fsum, *p_msum, *p_cnt, *p_Pr, *p_Pc;
    cudaGetSymbolAddress((void**)&p_h0, g_h0);
    cudaGetSymbolAddress((void**)&p_h1, g_h1);
    cudaGetSymbolAddress((void**)&p_equ1, g_equ1);
    cudaGetSymbolAddress((void**)&p_fsum, g_fsum);
    cudaGetSymbolAddress((void**)&p_msum, g_msum);
    cudaGetSymbolAddress((void**)&p_cnt, g_cnt);
    cudaGetSymbolAddress((void**)&p_Pr, g_Pr);
    cudaGetSymbolAddress((void**)&p_Pc, g_Pc);

    cudaMemsetAsync(p_cnt, 0, NN * sizeof(float));
    deg_kernel<<<(EE + 255) / 256, 256>>>(erow, p_cnt);
    embed_kernel<<<NN, 128>>>(h_in, embW, embB, p_h0);

    const int nblk = (NN + 63) / 64;

    for (int i = 0; i < 2; i++) {
        const float* h_cur   = (i == 0) ? p_h0 : p_h1;
        const float* equ_cur = (i == 0) ? equ : p_equ1;
        float* equ_nxt = (i == 0) ? p_equ1 : out;
        float* h_nxt   = (i == 0) ? p_h1 : (out + NN * 9);

        cudaMemsetAsync(p_fsum, 0, NN * 12 * sizeof(float));
        cudaMemsetAsync(p_msum, 0, (size_t)NN * HH * sizeof(float));

        prep_kernel<<<nblk, 256, P_SMEM_BYTES>>>(
            h_cur, msgW1 + (size_t)i * 267 * 128, msgB1 + i * 128, p_Pr, p_Pc, NN);

        edge_kernel<<<EE / 64, 256, E_SMEM_BYTES>>>(
            equ_cur, p_Pr, p_Pc, efea, erow, ecol,
            msgW1 + (size_t)i * 267 * 128,
            msgW2 + (size_t)i * 128 * 128, msgB2 + i * 128,
            cW1 + (size_t)i * 128 * 128, cB1 + i * 128,
            cW2 + (size_t)i * 128, cB2 + i,
            p_fsum, p_msum);

        node_kernel<<<nblk, 256, N_SMEM_BYTES>>>(
            h_cur, equ_cur, p_fsum, p_msum, p_cnt,
            nW1 + (size_t)i * 256 * 128, nB1 + i * 128,
            nW2 + (size_t)i * 128 * 128, nB2 + i * 128,
            qW1 + (size_t)i * 128 * 128, qB1 + i * 128,
            qW2 + (size_t)i * 128, qB2 + i,
            equ_nxt, h_nxt, NN);
    }
}